// round 2
// baseline (speedup 1.0000x reference)
#include <cuda_runtime.h>
#include <math.h>

#define BB 2
#define LL 4096
#define EE 1024
#define HH 16
#define DH 64
#define CH 256
#define NCH 16
#define M1 (BB*LL)   // 8192

// ---------------- scratch (static device globals; no allocation) ----------------
__device__ float g_q[(size_t)BB*HH*LL*DH];        // [B,H,L,D]  feature-mapped, scaled
__device__ float g_k[(size_t)BB*HH*LL*DH];        // [B,H,L,D]  feature-mapped
__device__ float g_v[(size_t)BB*HH*LL*DH];        // [B,H,L,D]
__device__ float g_G[(size_t)BB*HH*NCH*DH*DH];    // per-chunk K^T V
__device__ float g_S[(size_t)BB*HH*NCH*DH*DH];    // exclusive prefix of G
__device__ float g_zc[(size_t)BB*HH*NCH*DH];      // per-chunk sum K
__device__ float g_Z[(size_t)BB*HH*NCH*DH];       // exclusive prefix of z
__device__ float g_att[(size_t)M1*EE];            // attention output, [B*L, E]

// ---------------- generic SGEMM: C[M,N] = A[M,K] * B[N,K]^T ----------------
// BM=BN=128, BK=16, 256 threads, 8x8 microtile.
// EPI==0: plain store to C (row stride Ndim).
// EPI==1: qkv epilogue -> feature map + scatter into g_q/g_k/g_v.
// ASRC==1: ignore A argument, read from g_att (device-side symbol resolution!)
template<int EPI, int ASRC>
__global__ __launch_bounds__(256)
void sgemm_kernel(const float* __restrict__ A_in, const float* __restrict__ Bw,
                  float* __restrict__ C, int Kdim, int Ndim)
{
    const float* __restrict__ A = (ASRC == 1) ? (const float*)g_att : A_in;

    __shared__ float As[16][132];
    __shared__ float Bs[16][132];

    const int tid = threadIdx.x;
    const int tx = tid & 15;          // 0..15 -> n microtile
    const int ty = tid >> 4;          // 0..15 -> m microtile
    const int m0 = blockIdx.y * 128;
    const int n0 = blockIdx.x * 128;

    float acc[8][8];
#pragma unroll
    for (int i = 0; i < 8; i++)
#pragma unroll
        for (int j = 0; j < 8; j++) acc[i][j] = 0.f;

    for (int kb = 0; kb < Kdim; kb += 16) {
        // load A tile (128 rows x 16 k) as float4, store transposed As[k][m]
#pragma unroll
        for (int t = 0; t < 2; t++) {
            int idx = tid + t * 256;          // 0..511 float4 slots
            int row = idx >> 2, kq = idx & 3;
            float4 va = *(const float4*)(A + (size_t)(m0 + row) * Kdim + kb + kq * 4);
            As[kq*4+0][row] = va.x; As[kq*4+1][row] = va.y;
            As[kq*4+2][row] = va.z; As[kq*4+3][row] = va.w;
        }
#pragma unroll
        for (int t = 0; t < 2; t++) {
            int idx = tid + t * 256;
            int row = idx >> 2, kq = idx & 3;
            float4 vb = *(const float4*)(Bw + (size_t)(n0 + row) * Kdim + kb + kq * 4);
            Bs[kq*4+0][row] = vb.x; Bs[kq*4+1][row] = vb.y;
            Bs[kq*4+2][row] = vb.z; Bs[kq*4+3][row] = vb.w;
        }
        __syncthreads();

#pragma unroll
        for (int kk = 0; kk < 16; kk++) {
            float a[8], b[8];
#pragma unroll
            for (int i = 0; i < 8; i++) a[i] = As[kk][ty*8 + i];
#pragma unroll
            for (int j = 0; j < 8; j++) b[j] = Bs[kk][tx*8 + j];
#pragma unroll
            for (int i = 0; i < 8; i++)
#pragma unroll
                for (int j = 0; j < 8; j++) acc[i][j] += a[i] * b[j];
        }
        __syncthreads();
    }

    if (EPI == 0) {
#pragma unroll
        for (int i = 0; i < 8; i++) {
            int m = m0 + ty*8 + i;
            float* crow = C + (size_t)m * Ndim + n0 + tx*8;
#pragma unroll
            for (int j = 0; j < 8; j++) crow[j] = acc[i][j];
        }
    } else {
        // n -> (s, h, d); m -> (b, l). Apply feature map and scatter.
#pragma unroll
        for (int i = 0; i < 8; i++) {
            int m = m0 + ty*8 + i;
            int bidx = m >> 12;           // /4096
            int l = m & 4095;
#pragma unroll
            for (int j = 0; j < 8; j++) {
                int n = n0 + tx*8 + j;
                int s = n >> 10;
                int h = (n >> 6) & 15;
                int d = n & 63;
                float val = acc[i][j];
                float r;
                if (s == 0)       r = (val > 0.f ? val + 1.f : expf(val)) * 0.125f;
                else if (s == 1)  r = (val > 0.f ? val + 1.f : expf(val));
                else              r = val;
                float* dst = (s == 0) ? g_q : (s == 1) ? g_k : g_v;
                dst[((size_t)(bidx*HH + h) * LL + l) * DH + d] = r;
            }
        }
    }
}

// ---------------- per-chunk Gram: G = K_c^T V_c  (64x64), z = sum K_c ----------------
__global__ __launch_bounds__(256)
void chunk_kv_kernel()
{
    const int c = blockIdx.x, h = blockIdx.y, b = blockIdx.z;
    const int bh = b * HH + h;
    const float* kc = g_k + ((size_t)bh * LL + c * CH) * DH;
    const float* vc = g_v + ((size_t)bh * LL + c * CH) * DH;

    __shared__ float ks[64][65];
    __shared__ float vs[64][65];

    const int tid = threadIdx.x;
    const int tx = tid & 15, ty = tid >> 4;

    float acc[4][4];
#pragma unroll
    for (int i = 0; i < 4; i++)
#pragma unroll
        for (int j = 0; j < 4; j++) acc[i][j] = 0.f;
    float zacc = 0.f;

    for (int lt = 0; lt < 4; lt++) {
#pragma unroll
        for (int t = 0; t < 4; t++) {
            int idx = tid + t * 256;      // 0..1023 float4 slots
            int row = idx >> 4, c4 = idx & 15;
            float4 kv = *(const float4*)(kc + (size_t)(lt*64 + row) * DH + c4 * 4);
            ks[row][c4*4+0] = kv.x; ks[row][c4*4+1] = kv.y;
            ks[row][c4*4+2] = kv.z; ks[row][c4*4+3] = kv.w;
            float4 vv = *(const float4*)(vc + (size_t)(lt*64 + row) * DH + c4 * 4);
            vs[row][c4*4+0] = vv.x; vs[row][c4*4+1] = vv.y;
            vs[row][c4*4+2] = vv.z; vs[row][c4*4+3] = vv.w;
        }
        __syncthreads();
#pragma unroll 8
        for (int l = 0; l < 64; l++) {
            float a[4], bb[4];
#pragma unroll
            for (int i = 0; i < 4; i++) a[i] = ks[l][ty*4 + i];
#pragma unroll
            for (int j = 0; j < 4; j++) bb[j] = vs[l][tx*4 + j];
#pragma unroll
            for (int i = 0; i < 4; i++)
#pragma unroll
                for (int j = 0; j < 4; j++) acc[i][j] += a[i] * bb[j];
        }
        if (tid < 64) {
#pragma unroll 8
            for (int l = 0; l < 64; l++) zacc += ks[l][tid];
        }
        __syncthreads();
    }

    float* Gout = g_G + ((size_t)bh * NCH + c) * DH * DH;
#pragma unroll
    for (int i = 0; i < 4; i++)
#pragma unroll
        for (int j = 0; j < 4; j++)
            Gout[(ty*4 + i) * DH + tx*4 + j] = acc[i][j];
    if (tid < 64) g_zc[((size_t)bh * NCH + c) * DH + tid] = zacc;
}

// ---------------- exclusive prefix over chunks ----------------
__global__ __launch_bounds__(256)
void prefix_kernel()
{
    const int bh = blockIdx.x;
    const int tid = threadIdx.x;
    for (int idx = tid; idx < DH*DH; idx += 256) {
        float run = 0.f;
        for (int c = 0; c < NCH; c++) {
            size_t o = ((size_t)bh * NCH + c) * DH * DH + idx;
            g_S[o] = run;
            run += g_G[o];
        }
    }
    if (tid < DH) {
        float run = 0.f;
        for (int c = 0; c < NCH; c++) {
            size_t o = ((size_t)bh * NCH + c) * DH + tid;
            g_Z[o] = run;
            run += g_zc[o];
        }
    }
}

// ---------------- attention core: per (b,h,c), 256x64 output tile ----------------
// num = (QK^T . tril) V  +  Q S_prefix ; den = rowsum + Q Z_prefix ; out = num/den
__global__ __launch_bounds__(256, 1)
void attn_core_kernel()
{
    const int c = blockIdx.x, h = blockIdx.y, b = blockIdx.z;
    const int bh = b * HH + h;
    const float* qc = g_q + ((size_t)bh * LL + c * CH) * DH;
    const float* kc = g_k + ((size_t)bh * LL + c * CH) * DH;
    const float* vc = g_v + ((size_t)bh * LL + c * CH) * DH;
    const float* Sc = g_S + ((size_t)bh * NCH + c) * DH * DH;
    const float* Zc = g_Z + ((size_t)bh * NCH + c) * DH;

    extern __shared__ float sm[];
    float* q_s = sm;                    // [256][65]
    float* p_s = sm + 256*65;           // [256][65]
    float* k_s = sm + 2*256*65;         // [64][65]
    float* v_s = k_s + 64*65;           // [64][65]
    float* S_s = v_s + 64*65;           // [64][65]
    float* Z_s = S_s + 64*65;           // [64]

    const int tid = threadIdx.x;
    const int tx = tid & 7;             // 0..7  -> 8 cols each
    const int ty = tid >> 3;            // 0..31 -> 8 rows each

    // load q chunk (256x64)
#pragma unroll
    for (int t = 0; t < 16; t++) {
        int idx = tid + t * 256;        // float4 slot, 0..4095
        int row = idx >> 4, c4 = idx & 15;
        float4 vq = *(const float4*)(qc + (size_t)row * DH + c4 * 4);
        float* dst = q_s + row*65 + c4*4;
        dst[0]=vq.x; dst[1]=vq.y; dst[2]=vq.z; dst[3]=vq.w;
    }
    // load S (64x64)
#pragma unroll
    for (int t = 0; t < 4; t++) {
        int idx = tid + t * 256;        // 0..1023
        int row = idx >> 4, c4 = idx & 15;
        float4 vv = *(const float4*)(Sc + (size_t)row * DH + c4 * 4);
        float* dst = S_s + row*65 + c4*4;
        dst[0]=vv.x; dst[1]=vv.y; dst[2]=vv.z; dst[3]=vv.w;
    }
    if (tid < DH) Z_s[tid] = Zc[tid];
    __syncthreads();

    float num[8][8];
#pragma unroll
    for (int i = 0; i < 8; i++)
#pragma unroll
        for (int j = 0; j < 8; j++) num[i][j] = 0.f;
    float den[8];
#pragma unroll
    for (int i = 0; i < 8; i++) den[i] = 0.f;

    for (int jb = 0; jb < 4; jb++) {
        // load k,v strip (64 rows)
#pragma unroll
        for (int t = 0; t < 4; t++) {
            int idx = tid + t * 256;
            int row = idx >> 4, c4 = idx & 15;
            float4 kv = *(const float4*)(kc + (size_t)(jb*64 + row) * DH + c4 * 4);
            float* dk = k_s + row*65 + c4*4;
            dk[0]=kv.x; dk[1]=kv.y; dk[2]=kv.z; dk[3]=kv.w;
            float4 vv = *(const float4*)(vc + (size_t)(jb*64 + row) * DH + c4 * 4);
            float* dv = v_s + row*65 + c4*4;
            dv[0]=vv.x; dv[1]=vv.y; dv[2]=vv.z; dv[3]=vv.w;
        }
        __syncthreads();

        // GEMM1: P = Q K_strip^T (256x64, K=64)
        float p[8][8];
#pragma unroll
        for (int i = 0; i < 8; i++)
#pragma unroll
            for (int j = 0; j < 8; j++) p[i][j] = 0.f;
#pragma unroll 8
        for (int d = 0; d < 64; d++) {
            float a[8], bb[8];
#pragma unroll
            for (int i = 0; i < 8; i++) a[i] = q_s[(ty*8 + i)*65 + d];
#pragma unroll
            for (int j = 0; j < 8; j++) bb[j] = k_s[(tx*8 + j)*65 + d];
#pragma unroll
            for (int i = 0; i < 8; i++)
#pragma unroll
                for (int j = 0; j < 8; j++) p[i][j] += a[i] * bb[j];
        }
        // causal mask, partial row sums, stage P to shared
#pragma unroll
        for (int i = 0; i < 8; i++) {
            int r = ty*8 + i;
#pragma unroll
            for (int j = 0; j < 8; j++) {
                int kk = jb*64 + tx*8 + j;
                float val = (kk <= r) ? p[i][j] : 0.f;
                den[i] += val;
                p_s[r*65 + tx*8 + j] = val;
            }
        }
        __syncthreads();

        // GEMM2: num += P V_strip (256x64, K=64)
#pragma unroll 8
        for (int m = 0; m < 64; m++) {
            float a[8], bb[8];
#pragma unroll
            for (int i = 0; i < 8; i++) a[i] = p_s[(ty*8 + i)*65 + m];
#pragma unroll
            for (int j = 0; j < 8; j++) bb[j] = v_s[m*65 + tx*8 + j];
#pragma unroll
            for (int i = 0; i < 8; i++)
#pragma unroll
                for (int j = 0; j < 8; j++) num[i][j] += a[i] * bb[j];
        }
        __syncthreads();
    }

    // inter-chunk: num += Q * S_prefix
#pragma unroll 8
    for (int d = 0; d < 64; d++) {
        float a[8], bb[8];
#pragma unroll
        for (int i = 0; i < 8; i++) a[i] = q_s[(ty*8 + i)*65 + d];
#pragma unroll
        for (int j = 0; j < 8; j++) bb[j] = S_s[d*65 + tx*8 + j];
#pragma unroll
        for (int i = 0; i < 8; i++)
#pragma unroll
            for (int j = 0; j < 8; j++) num[i][j] += a[i] * bb[j];
    }

    // reduce den across the 8 tx lanes (same ty group = 8 consecutive lanes)
#pragma unroll
    for (int i = 0; i < 8; i++) {
#pragma unroll
        for (int off = 1; off < 8; off <<= 1)
            den[i] += __shfl_xor_sync(0xffffffffu, den[i], off);
    }
    // add inter-chunk den: q . Z (redundant per lane, after reduction)
#pragma unroll
    for (int i = 0; i < 8; i++) {
        int r = ty*8 + i;
        float dz = 0.f;
#pragma unroll 8
        for (int d = 0; d < 64; d++) dz += q_s[r*65 + d] * Z_s[d];
        den[i] += dz;
    }

    // write out: attn_out[b*L + c*256 + r, h*64 + e]
    const size_t mbase = (size_t)(b * LL + c * CH);
#pragma unroll
    for (int i = 0; i < 8; i++) {
        int r = ty*8 + i;
        float dd = fmaxf(den[i], 1e-6f);
        float inv = 1.f / dd;
        float* orow = g_att + (mbase + r) * EE + h * DH + tx*8;
#pragma unroll
        for (int j = 0; j < 8; j++) orow[j] = num[i][j] * inv;
    }
}

// ---------------- launch ----------------
extern "C" void kernel_launch(void* const* d_in, const int* in_sizes, int n_in,
                              void* d_out, int out_size)
{
    const float* x    = (const float*)d_in[0];   // [B, L, E]
    const float* Wqkv = (const float*)d_in[1];   // [3E, E]
    const float* Wout = (const float*)d_in[2];   // [E, E]
    float* out = (float*)d_out;                  // [B, L, E]

    // attn_core dynamic smem: (2*256*65 + 3*64*65 + 64) floats = 183,296 B
    const size_t attn_smem = (size_t)(2*256*65 + 3*64*65 + 64) * sizeof(float);
    cudaFuncSetAttribute(attn_core_kernel,
                         cudaFuncAttributeMaxDynamicSharedMemorySize, (int)attn_smem);

    // 1) QKV GEMM + feature map scatter: [8192,1024] x [3072,1024]^T
    {
        dim3 grid(3*EE/128, M1/128);  // (24, 64)
        sgemm_kernel<1,0><<<grid, 256>>>(x, Wqkv, nullptr, EE, 3*EE);
    }
    // 2) per-chunk Gram matrices
    {
        dim3 grid(NCH, HH, BB);       // (16,16,2)
        chunk_kv_kernel<<<grid, 256>>>();
    }
    // 3) exclusive prefix over chunks
    prefix_kernel<<<BB*HH, 256>>>();
    // 4) attention core
    {
        dim3 grid(NCH, HH, BB);
        attn_core_kernel<<<grid, 256, attn_smem>>>();
    }
    // 5) output GEMM: out = g_att @ Wout^T  (A taken from device symbol inside kernel)
    {
        dim3 grid(EE/128, M1/128);    // (8, 64)
        sgemm_kernel<0,1><<<grid, 256>>>(nullptr, Wout, out, EE, EE);
    }
}

// round 5
// speedup vs baseline: 2.0436x; 2.0436x over previous
#include <cuda_runtime.h>
#include <cuda_bf16.h>
#include <math.h>
#include <stdint.h>

#define BB 2
#define LL 4096
#define EE 1024
#define HH 16
#define DH 64
#define CH 256
#define NCH 16
#define M1 (BB*LL)      // 8192
#define NQKV (3*EE)     // 3072

// ---------------- scratch (static device globals; no allocation) ----------------
__device__ __nv_bfloat16 g_xhi[(size_t)M1*EE],   g_xlo[(size_t)M1*EE];
__device__ __nv_bfloat16 g_wqkv_hi[(size_t)NQKV*EE], g_wqkv_lo[(size_t)NQKV*EE];
__device__ __nv_bfloat16 g_wout_hi[(size_t)EE*EE],   g_wout_lo[(size_t)EE*EE];
__device__ __nv_bfloat16 g_att_hi[(size_t)M1*EE],    g_att_lo[(size_t)M1*EE];

__device__ float g_q[(size_t)BB*HH*LL*DH];
__device__ float g_k[(size_t)BB*HH*LL*DH];
__device__ float g_v[(size_t)BB*HH*LL*DH];
__device__ float g_G[(size_t)BB*HH*NCH*DH*DH];
__device__ float g_S[(size_t)BB*HH*NCH*DH*DH];
__device__ float g_zc[(size_t)BB*HH*NCH*DH];
__device__ float g_Z[(size_t)BB*HH*NCH*DH];

// ---------------- helpers ----------------
__device__ __forceinline__ uint32_t smem_u32(const void* p) {
    uint32_t a;
    asm("{ .reg .u64 t; cvta.to.shared.u64 t, %1; cvt.u32.u64 %0, t; }" : "=r"(a) : "l"(p));
    return a;
}
__device__ __forceinline__ void ldmx4(uint32_t* r, uint32_t a) {
    asm volatile("ldmatrix.sync.aligned.m8n8.x4.shared.b16 {%0,%1,%2,%3}, [%4];"
        : "=r"(r[0]), "=r"(r[1]), "=r"(r[2]), "=r"(r[3]) : "r"(a));
}
__device__ __forceinline__ void mma_bf16(float* d, const uint32_t* a, const uint32_t* b) {
    asm volatile(
        "mma.sync.aligned.m16n8k16.row.col.f32.bf16.bf16.f32 "
        "{%0,%1,%2,%3}, {%4,%5,%6,%7}, {%8,%9}, {%0,%1,%2,%3};"
        : "+f"(d[0]), "+f"(d[1]), "+f"(d[2]), "+f"(d[3])
        : "r"(a[0]), "r"(a[1]), "r"(a[2]), "r"(a[3]), "r"(b[0]), "r"(b[1]));
}

// ---------------- fp32 -> (hi,lo) bf16 split converter ----------------
template<int W>
__global__ __launch_bounds__(256)
void convert_kernel(const float* __restrict__ src, int n4)
{
    __nv_bfloat16 *hi, *lo;
    if (W == 0)      { hi = g_xhi;     lo = g_xlo; }
    else if (W == 1) { hi = g_wqkv_hi; lo = g_wqkv_lo; }
    else             { hi = g_wout_hi; lo = g_wout_lo; }
    int i = blockIdx.x * 256 + threadIdx.x;
    if (i >= n4) return;
    float4 v = ((const float4*)src)[i];
    float a[4] = {v.x, v.y, v.z, v.w};
    __nv_bfloat16 h[4], l[4];
#pragma unroll
    for (int j = 0; j < 4; j++) {
        h[j] = __float2bfloat16(a[j]);
        l[j] = __float2bfloat16(a[j] - __bfloat162float(h[j]));
    }
    ((__nv_bfloat162*)hi)[i*2 + 0] = __nv_bfloat162(h[0], h[1]);
    ((__nv_bfloat162*)hi)[i*2 + 1] = __nv_bfloat162(h[2], h[3]);
    ((__nv_bfloat162*)lo)[i*2 + 0] = __nv_bfloat162(l[0], l[1]);
    ((__nv_bfloat162*)lo)[i*2 + 1] = __nv_bfloat162(l[2], l[3]);
}

// ---------------- HMMA (mma.sync) GEMM, split-bf16 3-term compensation ----------------
// C[M,N] = A[M,K] * B[N,K]^T = hi*hi + hi*lo + lo*hi, fp32 accumulate.
// MODE 0: A=g_x*, B=g_wqkv* (N=3072), epilogue feature map -> g_q/g_k/g_v
// MODE 1: A=g_att*, B=g_wout* (N=1024), plain fp32 store to C
// Block 128x128, BK=64, 8 warps (2x4), warp tile 64x32. smem pitch 144 B.
#define PITCH 144
#define TILE_BYTES (128*PITCH)   // 18432

template<int MODE>
__global__ __launch_bounds__(256, 2)
void hmma_gemm_kernel(float* __restrict__ C)
{
    const __nv_bfloat16* __restrict__ Ahi = (MODE == 0) ? g_xhi : g_att_hi;
    const __nv_bfloat16* __restrict__ Alo = (MODE == 0) ? g_xlo : g_att_lo;
    const __nv_bfloat16* __restrict__ Bhi = (MODE == 0) ? g_wqkv_hi : g_wout_hi;
    const __nv_bfloat16* __restrict__ Blo = (MODE == 0) ? g_wqkv_lo : g_wout_lo;

    const int m0 = blockIdx.y * 128;
    const int n0 = blockIdx.x * 128;
    const int tid = threadIdx.x;
    const int wid = tid >> 5;
    const int lane = tid & 31;
    const int wm = (wid >> 2) * 64;   // 0 or 64
    const int wn = (wid & 3) * 32;    // 0..96

    extern __shared__ char smc[];
    char* sAhi = smc;
    char* sAlo = smc + TILE_BYTES;
    char* sBhi = smc + 2*TILE_BYTES;
    char* sBlo = smc + 3*TILE_BYTES;
    const uint32_t base = smem_u32(smc);

    float acc[4][4][4];
#pragma unroll
    for (int a = 0; a < 4; a++)
#pragma unroll
        for (int b = 0; b < 4; b++)
#pragma unroll
            for (int c = 0; c < 4; c++) acc[a][b][c] = 0.f;

    // per-lane ldmatrix address components
    const int g = lane >> 3, lr = lane & 7;
    const int a_row  = ((g & 1) << 3) + lr;        // + wm + mi*16
    const int a_xtra = (g & 2) ? 16 : 0;
    const int b_row  = ((g >> 1) << 3) + lr;       // + wn + np*16
    const int b_xtra = (g & 1) ? 16 : 0;

    for (int kc = 0; kc < 16; kc++) {
        const int kb = kc * 64;
        // load 4 tiles: each 128 rows x 128 B (64 bf16), 1024 uint4 slots
#pragma unroll
        for (int t = 0; t < 4; t++) {
            int idx = tid + t * 256;
            int row = idx >> 3, c16 = idx & 7;
            size_t ga = (size_t)(m0 + row) * EE + kb + c16 * 8;
            size_t gb = (size_t)(n0 + row) * EE + kb + c16 * 8;
            uint32_t so = (uint32_t)(row * PITCH + c16 * 16);
            *(uint4*)(sAhi + so) = *(const uint4*)(Ahi + ga);
            *(uint4*)(sAlo + so) = *(const uint4*)(Alo + ga);
            *(uint4*)(sBhi + so) = *(const uint4*)(Bhi + gb);
            *(uint4*)(sBlo + so) = *(const uint4*)(Blo + gb);
        }
        __syncthreads();

#pragma unroll
        for (int t = 0; t < 4; t++) {
            // B fragments: 2 ldmatrix.x4 per operand half (covers 4 n8 tiles)
            uint32_t bfh[8], bfl[8];
#pragma unroll
            for (int np = 0; np < 2; np++) {
                uint32_t off = (uint32_t)((wn + np*16 + b_row) * PITCH + t*32 + b_xtra);
                ldmx4(bfh + np*4, base + 2*TILE_BYTES + off);
                ldmx4(bfl + np*4, base + 3*TILE_BYTES + off);
            }
#pragma unroll
            for (int mi = 0; mi < 4; mi++) {
                uint32_t afh[4], afl[4];
                uint32_t off = (uint32_t)((wm + mi*16 + a_row) * PITCH + t*32 + a_xtra);
                ldmx4(afh, base + off);
                ldmx4(afl, base + TILE_BYTES + off);
#pragma unroll
                for (int ni = 0; ni < 4; ni++) {
                    const uint32_t* bh = &bfh[(ni >> 1)*4 + (ni & 1)*2];
                    const uint32_t* bl = &bfl[(ni >> 1)*4 + (ni & 1)*2];
                    mma_bf16(acc[mi][ni], afh, bh);
                    mma_bf16(acc[mi][ni], afh, bl);
                    mma_bf16(acc[mi][ni], afl, bh);
                }
            }
        }
        __syncthreads();
    }

    // epilogue
#pragma unroll
    for (int mi = 0; mi < 4; mi++) {
        int mrow = m0 + wm + mi*16 + (lane >> 2);
#pragma unroll
        for (int half = 0; half < 2; half++) {
            int m = mrow + half * 8;
#pragma unroll
            for (int ni = 0; ni < 4; ni++) {
                int n = n0 + wn + ni*8 + (lane & 3)*2;
                float v0 = acc[mi][ni][half*2 + 0];
                float v1 = acc[mi][ni][half*2 + 1];
                if (MODE == 1) {
                    *(float2*)(C + (size_t)m * EE + n) = make_float2(v0, v1);
                } else {
                    int s = n >> 10, h = (n >> 6) & 15, d = n & 63;
                    int bidx = m >> 12, l = m & 4095;
                    float r0, r1;
                    if (s == 0) {
                        r0 = (v0 > 0.f ? v0 + 1.f : expf(v0)) * 0.125f;
                        r1 = (v1 > 0.f ? v1 + 1.f : expf(v1)) * 0.125f;
                    } else if (s == 1) {
                        r0 = (v0 > 0.f ? v0 + 1.f : expf(v0));
                        r1 = (v1 > 0.f ? v1 + 1.f : expf(v1));
                    } else {
                        r0 = v0; r1 = v1;
                    }
                    float* dst = (s == 0) ? g_q : (s == 1) ? g_k : g_v;
                    *(float2*)(dst + ((size_t)(bidx*HH + h) * LL + l) * DH + d)
                        = make_float2(r0, r1);
                }
            }
        }
    }
}

// ---------------- per-chunk Gram: G = K_c^T V_c  (64x64), z = sum K_c ----------------
__global__ __launch_bounds__(256)
void chunk_kv_kernel()
{
    const int c = blockIdx.x, h = blockIdx.y, b = blockIdx.z;
    const int bh = b * HH + h;
    const float* kc = g_k + ((size_t)bh * LL + c * CH) * DH;
    const float* vc = g_v + ((size_t)bh * LL + c * CH) * DH;

    __shared__ float ks[64][65];
    __shared__ float vs[64][65];

    const int tid = threadIdx.x;
    const int tx = tid & 15, ty = tid >> 4;

    float acc[4][4];
#pragma unroll
    for (int i = 0; i < 4; i++)
#pragma unroll
        for (int j = 0; j < 4; j++) acc[i][j] = 0.f;
    float zacc = 0.f;

    for (int lt = 0; lt < 4; lt++) {
#pragma unroll
        for (int t = 0; t < 4; t++) {
            int idx = tid + t * 256;
            int row = idx >> 4, c4 = idx & 15;
            float4 kv = *(const float4*)(kc + (size_t)(lt*64 + row) * DH + c4 * 4);
            ks[row][c4*4+0] = kv.x; ks[row][c4*4+1] = kv.y;
            ks[row][c4*4+2] = kv.z; ks[row][c4*4+3] = kv.w;
            float4 vv = *(const float4*)(vc + (size_t)(lt*64 + row) * DH + c4 * 4);
            vs[row][c4*4+0] = vv.x; vs[row][c4*4+1] = vv.y;
            vs[row][c4*4+2] = vv.z; vs[row][c4*4+3] = vv.w;
        }
        __syncthreads();
#pragma unroll 8
        for (int l = 0; l < 64; l++) {
            float a[4], bb[4];
#pragma unroll
            for (int i = 0; i < 4; i++) a[i] = ks[l][ty*4 + i];
#pragma unroll
            for (int j = 0; j < 4; j++) bb[j] = vs[l][tx*4 + j];
#pragma unroll
            for (int i = 0; i < 4; i++)
#pragma unroll
                for (int j = 0; j < 4; j++) acc[i][j] += a[i] * bb[j];
        }
        if (tid < 64) {
#pragma unroll 8
            for (int l = 0; l < 64; l++) zacc += ks[l][tid];
        }
        __syncthreads();
    }

    float* Gout = g_G + ((size_t)bh * NCH + c) * DH * DH;
#pragma unroll
    for (int i = 0; i < 4; i++)
#pragma unroll
        for (int j = 0; j < 4; j++)
            Gout[(ty*4 + i) * DH + tx*4 + j] = acc[i][j];
    if (tid < 64) g_zc[((size_t)bh * NCH + c) * DH + tid] = zacc;
}

// ---------------- exclusive prefix over chunks ----------------
__global__ __launch_bounds__(256)
void prefix_kernel()
{
    const int bh = blockIdx.x;
    const int tid = threadIdx.x;
    for (int idx = tid; idx < DH*DH; idx += 256) {
        float run = 0.f;
        for (int c = 0; c < NCH; c++) {
            size_t o = ((size_t)bh * NCH + c) * DH * DH + idx;
            g_S[o] = run;
            run += g_G[o];
        }
    }
    if (tid < DH) {
        float run = 0.f;
        for (int c = 0; c < NCH; c++) {
            size_t o = ((size_t)bh * NCH + c) * DH + tid;
            g_Z[o] = run;
            run += g_zc[o];
        }
    }
}

// ---------------- attention core: per (b,h,c), 256x64 output tile ----------------
__global__ __launch_bounds__(256, 1)
void attn_core_kernel()
{
    const int c = blockIdx.x, h = blockIdx.y, b = blockIdx.z;
    const int bh = b * HH + h;
    const float* qc = g_q + ((size_t)bh * LL + c * CH) * DH;
    const float* kc = g_k + ((size_t)bh * LL + c * CH) * DH;
    const float* vc = g_v + ((size_t)bh * LL + c * CH) * DH;
    const float* Sc = g_S + ((size_t)bh * NCH + c) * DH * DH;
    const float* Zc = g_Z + ((size_t)bh * NCH + c) * DH;

    extern __shared__ float sm[];
    float* q_s = sm;                    // [256][65]
    float* p_s = sm + 256*65;           // [256][65]
    float* k_s = sm + 2*256*65;         // [64][65]
    float* v_s = k_s + 64*65;           // [64][65]
    float* S_s = v_s + 64*65;           // [64][65]
    float* Z_s = S_s + 64*65;           // [64]

    const int tid = threadIdx.x;
    const int tx = tid & 7;
    const int ty = tid >> 3;

#pragma unroll
    for (int t = 0; t < 16; t++) {
        int idx = tid + t * 256;
        int row = idx >> 4, c4 = idx & 15;
        float4 vq = *(const float4*)(qc + (size_t)row * DH + c4 * 4);
        float* dst = q_s + row*65 + c4*4;
        dst[0]=vq.x; dst[1]=vq.y; dst[2]=vq.z; dst[3]=vq.w;
    }
#pragma unroll
    for (int t = 0; t < 4; t++) {
        int idx = tid + t * 256;
        int row = idx >> 4, c4 = idx & 15;
        float4 vv = *(const float4*)(Sc + (size_t)row * DH + c4 * 4);
        float* dst = S_s + row*65 + c4*4;
        dst[0]=vv.x; dst[1]=vv.y; dst[2]=vv.z; dst[3]=vv.w;
    }
    if (tid < DH) Z_s[tid] = Zc[tid];
    __syncthreads();

    float num[8][8];
#pragma unroll
    for (int i = 0; i < 8; i++)
#pragma unroll
        for (int j = 0; j < 8; j++) num[i][j] = 0.f;
    float den[8];
#pragma unroll
    for (int i = 0; i < 8; i++) den[i] = 0.f;

    for (int jb = 0; jb < 4; jb++) {
#pragma unroll
        for (int t = 0; t < 4; t++) {
            int idx = tid + t * 256;
            int row = idx >> 4, c4 = idx & 15;
            float4 kv = *(const float4*)(kc + (size_t)(jb*64 + row) * DH + c4 * 4);
            float* dk = k_s + row*65 + c4*4;
            dk[0]=kv.x; dk[1]=kv.y; dk[2]=kv.z; dk[3]=kv.w;
            float4 vv = *(const float4*)(vc + (size_t)(jb*64 + row) * DH + c4 * 4);
            float* dv = v_s + row*65 + c4*4;
            dv[0]=vv.x; dv[1]=vv.y; dv[2]=vv.z; dv[3]=vv.w;
        }
        __syncthreads();

        float p[8][8];
#pragma unroll
        for (int i = 0; i < 8; i++)
#pragma unroll
            for (int j = 0; j < 8; j++) p[i][j] = 0.f;
#pragma unroll 8
        for (int d = 0; d < 64; d++) {
            float a[8], bb[8];
#pragma unroll
            for (int i = 0; i < 8; i++) a[i] = q_s[(ty*8 + i)*65 + d];
#pragma unroll
            for (int j = 0; j < 8; j++) bb[j] = k_s[(tx*8 + j)*65 + d];
#pragma unroll
            for (int i = 0; i < 8; i++)
#pragma unroll
                for (int j = 0; j < 8; j++) p[i][j] += a[i] * bb[j];
        }
#pragma unroll
        for (int i = 0; i < 8; i++) {
            int r = ty*8 + i;
#pragma unroll
            for (int j = 0; j < 8; j++) {
                int kk = jb*64 + tx*8 + j;
                float val = (kk <= r) ? p[i][j] : 0.f;
                den[i] += val;
                p_s[r*65 + tx*8 + j] = val;
            }
        }
        __syncthreads();

#pragma unroll 8
        for (int m = 0; m < 64; m++) {
            float a[8], bb[8];
#pragma unroll
            for (int i = 0; i < 8; i++) a[i] = p_s[(ty*8 + i)*65 + m];
#pragma unroll
            for (int j = 0; j < 8; j++) bb[j] = v_s[m*65 + tx*8 + j];
#pragma unroll
            for (int i = 0; i < 8; i++)
#pragma unroll
                for (int j = 0; j < 8; j++) num[i][j] += a[i] * bb[j];
        }
        __syncthreads();
    }

#pragma unroll 8
    for (int d = 0; d < 64; d++) {
        float a[8], bb[8];
#pragma unroll
        for (int i = 0; i < 8; i++) a[i] = q_s[(ty*8 + i)*65 + d];
#pragma unroll
        for (int j = 0; j < 8; j++) bb[j] = S_s[d*65 + tx*8 + j];
#pragma unroll
        for (int i = 0; i < 8; i++)
#pragma unroll
            for (int j = 0; j < 8; j++) num[i][j] += a[i] * bb[j];
    }

#pragma unroll
    for (int i = 0; i < 8; i++) {
#pragma unroll
        for (int off = 1; off < 8; off <<= 1)
            den[i] += __shfl_xor_sync(0xffffffffu, den[i], off);
    }
#pragma unroll
    for (int i = 0; i < 8; i++) {
        int r = ty*8 + i;
        float dz = 0.f;
#pragma unroll 8
        for (int d = 0; d < 64; d++) dz += q_s[r*65 + d] * Z_s[d];
        den[i] += dz;
    }

    // write out as split bf16 for the tensor-core output GEMM
    const size_t mbase = (size_t)(b * LL + c * CH);
#pragma unroll
    for (int i = 0; i < 8; i++) {
        int r = ty*8 + i;
        float dd = fmaxf(den[i], 1e-6f);
        float inv = 1.f / dd;
        size_t obase = (mbase + r) * EE + h * DH + tx*8;
#pragma unroll
        for (int j = 0; j < 8; j++) {
            float o = num[i][j] * inv;
            __nv_bfloat16 ohi = __float2bfloat16(o);
            g_att_hi[obase + j] = ohi;
            g_att_lo[obase + j] = __float2bfloat16(o - __bfloat162float(ohi));
        }
    }
}

// ---------------- launch ----------------
extern "C" void kernel_launch(void* const* d_in, const int* in_sizes, int n_in,
                              void* d_out, int out_size)
{
    const float* x    = (const float*)d_in[0];   // [B, L, E]
    const float* Wqkv = (const float*)d_in[1];   // [3E, E]
    const float* Wout = (const float*)d_in[2];   // [E, E]
    float* out = (float*)d_out;                  // [B, L, E]

    const size_t attn_smem = (size_t)(2*256*65 + 3*64*65 + 64) * sizeof(float);
    cudaFuncSetAttribute(attn_core_kernel,
                         cudaFuncAttributeMaxDynamicSharedMemorySize, (int)attn_smem);
    const int gemm_smem = 4 * TILE_BYTES;  // 73728
    cudaFuncSetAttribute(hmma_gemm_kernel<0>,
                         cudaFuncAttributeMaxDynamicSharedMemorySize, gemm_smem);
    cudaFuncSetAttribute(hmma_gemm_kernel<1>,
                         cudaFuncAttributeMaxDynamicSharedMemorySize, gemm_smem);

    // 0) split-bf16 conversion of inputs
    convert_kernel<0><<<(M1*EE/4 + 255)/256, 256>>>(x, M1*EE/4);
    convert_kernel<1><<<(NQKV*EE/4 + 255)/256, 256>>>(Wqkv, NQKV*EE/4);
    convert_kernel<2><<<(EE*EE/4 + 255)/256, 256>>>(Wout, EE*EE/4);

    // 1) QKV GEMM (mma.sync) + feature-map scatter
    {
        dim3 grid(NQKV/128, M1/128);  // (24, 64)
        hmma_gemm_kernel<0><<<grid, 256, gemm_smem>>>(nullptr);
    }
    // 2) per-chunk Gram matrices
    {
        dim3 grid(NCH, HH, BB);
        chunk_kv_kernel<<<grid, 256>>>();
    }
    // 3) exclusive prefix over chunks
    prefix_kernel<<<BB*HH, 256>>>();
    // 4) attention core (writes split-bf16 g_att)
    {
        dim3 grid(NCH, HH, BB);
        attn_core_kernel<<<grid, 256, attn_smem>>>();
    }
    // 5) output GEMM (mma.sync): out = att @ Wout^T
    {
        dim3 grid(EE/128, M1/128);    // (8, 64)
        hmma_gemm_kernel<1><<<grid, 256, gemm_smem>>>(out);
    }
}

// round 6
// speedup vs baseline: 2.2156x; 1.0842x over previous
#include <cuda_runtime.h>
#include <cuda_bf16.h>
#include <math.h>
#include <stdint.h>

#define BB 2
#define LL 4096
#define EE 1024
#define HH 16
#define DH 64
#define CH 256
#define NCH 16
#define M1 (BB*LL)      // 8192
#define NQKV (3*EE)     // 3072

// ---------------- scratch (static device globals; no allocation) ----------------
__device__ __align__(16) __nv_bfloat16 g_xhi[(size_t)M1*EE],   g_xlo[(size_t)M1*EE];
__device__ __align__(16) __nv_bfloat16 g_wqkv_hi[(size_t)NQKV*EE], g_wqkv_lo[(size_t)NQKV*EE];
__device__ __align__(16) __nv_bfloat16 g_wout_hi[(size_t)EE*EE],   g_wout_lo[(size_t)EE*EE];
__device__ __align__(16) __nv_bfloat16 g_att_hi[(size_t)M1*EE],    g_att_lo[(size_t)M1*EE];

__device__ __align__(16) __nv_bfloat16 g_q_hi[(size_t)BB*HH*LL*DH], g_q_lo[(size_t)BB*HH*LL*DH];
__device__ __align__(16) __nv_bfloat16 g_k_hi[(size_t)BB*HH*LL*DH], g_k_lo[(size_t)BB*HH*LL*DH];
__device__ __align__(16) __nv_bfloat16 g_v_hi[(size_t)BB*HH*LL*DH], g_v_lo[(size_t)BB*HH*LL*DH];

__device__ float g_G[(size_t)BB*HH*NCH*DH*DH];
__device__ __align__(16) __nv_bfloat16 g_ST_hi[(size_t)BB*HH*NCH*DH*DH], g_ST_lo[(size_t)BB*HH*NCH*DH*DH];
__device__ float g_zc[(size_t)BB*HH*NCH*DH];
__device__ float g_Z[(size_t)BB*HH*NCH*DH];

// ---------------- helpers ----------------
__device__ __forceinline__ uint32_t smem_u32(const void* p) {
    uint32_t a;
    asm("{ .reg .u64 t; cvta.to.shared.u64 t, %1; cvt.u32.u64 %0, t; }" : "=r"(a) : "l"(p));
    return a;
}
__device__ __forceinline__ void ldmx4(uint32_t* r, uint32_t a) {
    asm volatile("ldmatrix.sync.aligned.m8n8.x4.shared.b16 {%0,%1,%2,%3}, [%4];"
        : "=r"(r[0]), "=r"(r[1]), "=r"(r[2]), "=r"(r[3]) : "r"(a));
}
__device__ __forceinline__ void mma_bf16(float* d, const uint32_t* a, const uint32_t* b) {
    asm volatile(
        "mma.sync.aligned.m16n8k16.row.col.f32.bf16.bf16.f32 "
        "{%0,%1,%2,%3}, {%4,%5,%6,%7}, {%8,%9}, {%0,%1,%2,%3};"
        : "+f"(d[0]), "+f"(d[1]), "+f"(d[2]), "+f"(d[3])
        : "r"(a[0]), "r"(a[1]), "r"(a[2]), "r"(a[3]), "r"(b[0]), "r"(b[1]));
}
__device__ __forceinline__ uint32_t pack_bf2(__nv_bfloat16 a, __nv_bfloat16 b) {
    __nv_bfloat162 t(a, b);
    return *(uint32_t*)&t;
}
// split two fp32 into packed (hi, lo) bf16x2
__device__ __forceinline__ void split2(float a, float b, uint32_t& hi, uint32_t& lo) {
    __nv_bfloat16 ha = __float2bfloat16(a), hb = __float2bfloat16(b);
    __nv_bfloat16 la = __float2bfloat16(a - __bfloat162float(ha));
    __nv_bfloat16 lb = __float2bfloat16(b - __bfloat162float(hb));
    hi = pack_bf2(ha, hb);
    lo = pack_bf2(la, lb);
}

#define CP_ASYNC16(s, g) \
    asm volatile("cp.async.cg.shared.global [%0], [%1], 16;" :: "r"(s), "l"(g))
#define CP_COMMIT() asm volatile("cp.async.commit_group;")
#define CP_WAIT1()  asm volatile("cp.async.wait_group 1;")
#define CP_WAIT0()  asm volatile("cp.async.wait_group 0;")

// ---------------- fp32 -> (hi,lo) bf16 split converter ----------------
template<int W>
__global__ __launch_bounds__(256)
void convert_kernel(const float* __restrict__ src, int n4)
{
    __nv_bfloat16 *hi, *lo;
    if (W == 0)      { hi = g_xhi;     lo = g_xlo; }
    else if (W == 1) { hi = g_wqkv_hi; lo = g_wqkv_lo; }
    else             { hi = g_wout_hi; lo = g_wout_lo; }
    int i = blockIdx.x * 256 + threadIdx.x;
    if (i >= n4) return;
    float4 v = ((const float4*)src)[i];
    float a[4] = {v.x, v.y, v.z, v.w};
    __nv_bfloat16 h[4], l[4];
#pragma unroll
    for (int j = 0; j < 4; j++) {
        h[j] = __float2bfloat16(a[j]);
        l[j] = __float2bfloat16(a[j] - __bfloat162float(h[j]));
    }
    ((__nv_bfloat162*)hi)[i*2 + 0] = __nv_bfloat162(h[0], h[1]);
    ((__nv_bfloat162*)hi)[i*2 + 1] = __nv_bfloat162(h[2], h[3]);
    ((__nv_bfloat162*)lo)[i*2 + 0] = __nv_bfloat162(l[0], l[1]);
    ((__nv_bfloat162*)lo)[i*2 + 1] = __nv_bfloat162(l[2], l[3]);
}

// ---------------- HMMA GEMM, cp.async double-buffered, BK=32 ----------------
// C[M,N] = A[M,K] * B[N,K]^T = hi*hi + hi*lo + lo*hi, fp32 accumulate.
// MODE 0: A=g_x*, B=g_wqkv* (N=3072), epilogue feature map -> bf16 hi/lo q/k/v
// MODE 1: A=g_att*, B=g_wout* (N=1024), plain fp32 store to C
// Block 128x128, 8 warps (2x4), warp tile 64x32. smem pitch 80 B per 32-bf16 row.
#define P2 80
#define TILE2 (128*P2)     // 10240
#define STAGE2 (4*TILE2)   // 40960

template<int MODE>
__global__ __launch_bounds__(256, 2)
void hmma_gemm_kernel(float* __restrict__ C)
{
    const __nv_bfloat16* __restrict__ Ahi = (MODE == 0) ? g_xhi : g_att_hi;
    const __nv_bfloat16* __restrict__ Alo = (MODE == 0) ? g_xlo : g_att_lo;
    const __nv_bfloat16* __restrict__ Bhi = (MODE == 0) ? g_wqkv_hi : g_wout_hi;
    const __nv_bfloat16* __restrict__ Blo = (MODE == 0) ? g_wqkv_lo : g_wout_lo;

    const int m0 = blockIdx.y * 128;
    const int n0 = blockIdx.x * 128;
    const int tid = threadIdx.x;
    const int wid = tid >> 5;
    const int lane = tid & 31;
    const int wm = (wid >> 2) * 64;
    const int wn = (wid & 3) * 32;

    extern __shared__ char smc[];
    const uint32_t base = smem_u32(smc);

    float acc[4][4][4];
#pragma unroll
    for (int a = 0; a < 4; a++)
#pragma unroll
        for (int b = 0; b < 4; b++)
#pragma unroll
            for (int c = 0; c < 4; c++) acc[a][b][c] = 0.f;

    const int g = lane >> 3, lr = lane & 7;
    const int a_row  = ((g & 1) << 3) + lr;
    const int a_xtra = (g & 2) ? 16 : 0;
    const int b_row  = ((g >> 1) << 3) + lr;
    const int b_xtra = (g & 1) ? 16 : 0;

    auto prefetch = [&](int kc, int stg) {
        const int kb = kc * 32;
        const uint32_t sb = base + stg * STAGE2;
#pragma unroll
        for (int i = 0; i < 2; i++) {
            int s = tid + i * 256;          // 0..511
            int row = s >> 2, c16 = s & 3;
            uint32_t so = (uint32_t)(row * P2 + c16 * 16);
            size_t ga = (size_t)(m0 + row) * EE + kb + c16 * 8;
            size_t gb = (size_t)(n0 + row) * EE + kb + c16 * 8;
            CP_ASYNC16(sb + so,           __cvta_generic_to_global(Ahi + ga));
            CP_ASYNC16(sb + TILE2 + so,   __cvta_generic_to_global(Alo + ga));
            CP_ASYNC16(sb + 2*TILE2 + so, __cvta_generic_to_global(Bhi + gb));
            CP_ASYNC16(sb + 3*TILE2 + so, __cvta_generic_to_global(Blo + gb));
        }
    };

    prefetch(0, 0); CP_COMMIT();

    for (int kc = 0; kc < 32; kc++) {
        const int stg = kc & 1;
        if (kc + 1 < 32) { prefetch(kc + 1, stg ^ 1); CP_COMMIT(); CP_WAIT1(); }
        else             { CP_WAIT0(); }
        __syncthreads();

        const uint32_t sb = base + stg * STAGE2;
#pragma unroll
        for (int t = 0; t < 2; t++) {
            uint32_t bfh[8], bfl[8];
#pragma unroll
            for (int np = 0; np < 2; np++) {
                uint32_t off = (uint32_t)((wn + np*16 + b_row) * P2 + t*32 + b_xtra);
                ldmx4(bfh + np*4, sb + 2*TILE2 + off);
                ldmx4(bfl + np*4, sb + 3*TILE2 + off);
            }
#pragma unroll
            for (int mi = 0; mi < 4; mi++) {
                uint32_t afh[4], afl[4];
                uint32_t off = (uint32_t)((wm + mi*16 + a_row) * P2 + t*32 + a_xtra);
                ldmx4(afh, sb + off);
                ldmx4(afl, sb + TILE2 + off);
#pragma unroll
                for (int ni = 0; ni < 4; ni++) {
                    const uint32_t* bh = &bfh[(ni >> 1)*4 + (ni & 1)*2];
                    const uint32_t* bl = &bfl[(ni >> 1)*4 + (ni & 1)*2];
                    mma_bf16(acc[mi][ni], afh, bh);
                    mma_bf16(acc[mi][ni], afh, bl);
                    mma_bf16(acc[mi][ni], afl, bh);
                }
            }
        }
        __syncthreads();
    }

    // epilogue
#pragma unroll
    for (int mi = 0; mi < 4; mi++) {
        int mrow = m0 + wm + mi*16 + (lane >> 2);
#pragma unroll
        for (int half = 0; half < 2; half++) {
            int m = mrow + half * 8;
#pragma unroll
            for (int ni = 0; ni < 4; ni++) {
                int n = n0 + wn + ni*8 + (lane & 3)*2;
                float v0 = acc[mi][ni][half*2 + 0];
                float v1 = acc[mi][ni][half*2 + 1];
                if (MODE == 1) {
                    *(float2*)(C + (size_t)m * EE + n) = make_float2(v0, v1);
                } else {
                    int s = n >> 10, h = (n >> 6) & 15, d = n & 63;
                    int bidx = m >> 12, l = m & 4095;
                    float r0, r1;
                    if (s == 0) {
                        r0 = (v0 > 0.f ? v0 + 1.f : expf(v0)) * 0.125f;
                        r1 = (v1 > 0.f ? v1 + 1.f : expf(v1)) * 0.125f;
                    } else if (s == 1) {
                        r0 = (v0 > 0.f ? v0 + 1.f : expf(v0));
                        r1 = (v1 > 0.f ? v1 + 1.f : expf(v1));
                    } else {
                        r0 = v0; r1 = v1;
                    }
                    uint32_t hi, lo;
                    split2(r0, r1, hi, lo);
                    __nv_bfloat16* dh = (s == 0) ? g_q_hi : (s == 1) ? g_k_hi : g_v_hi;
                    __nv_bfloat16* dl = (s == 0) ? g_q_lo : (s == 1) ? g_k_lo : g_v_lo;
                    size_t off = ((size_t)(bidx*HH + h) * LL + l) * DH + d;
                    *(uint32_t*)(dh + off) = hi;
                    *(uint32_t*)(dl + off) = lo;
                }
            }
        }
    }
}

// ---------------- per-chunk Gram: G = K_c^T V_c  (64x64), z = sum K_c ----------------
__global__ __launch_bounds__(256)
void chunk_kv_kernel()
{
    const int c = blockIdx.x, h = blockIdx.y, b = blockIdx.z;
    const int bh = b * HH + h;
    const size_t tokbase = ((size_t)bh * LL + c * CH) * DH;
    const __nv_bfloat16* kh = g_k_hi + tokbase;
    const __nv_bfloat16* kl = g_k_lo + tokbase;
    const __nv_bfloat16* vh = g_v_hi + tokbase;
    const __nv_bfloat16* vl = g_v_lo + tokbase;

    __shared__ float ks[64][65];
    __shared__ float vs[64][65];

    const int tid = threadIdx.x;
    const int tx = tid & 15, ty = tid >> 4;

    float acc[4][4];
#pragma unroll
    for (int i = 0; i < 4; i++)
#pragma unroll
        for (int j = 0; j < 4; j++) acc[i][j] = 0.f;
    float zacc = 0.f;

    for (int lt = 0; lt < 4; lt++) {
#pragma unroll
        for (int t = 0; t < 4; t++) {
            int idx = tid + t * 256;
            int row = idx >> 4, c4 = idx & 15;
            size_t off = (size_t)(lt*64 + row) * DH + c4 * 4;
            __nv_bfloat162 a0 = *(const __nv_bfloat162*)(kh + off);
            __nv_bfloat162 a1 = *(const __nv_bfloat162*)(kh + off + 2);
            __nv_bfloat162 b0 = *(const __nv_bfloat162*)(kl + off);
            __nv_bfloat162 b1 = *(const __nv_bfloat162*)(kl + off + 2);
            ks[row][c4*4+0] = __bfloat162float(a0.x) + __bfloat162float(b0.x);
            ks[row][c4*4+1] = __bfloat162float(a0.y) + __bfloat162float(b0.y);
            ks[row][c4*4+2] = __bfloat162float(a1.x) + __bfloat162float(b1.x);
            ks[row][c4*4+3] = __bfloat162float(a1.y) + __bfloat162float(b1.y);
            __nv_bfloat162 c0 = *(const __nv_bfloat162*)(vh + off);
            __nv_bfloat162 c1 = *(const __nv_bfloat162*)(vh + off + 2);
            __nv_bfloat162 d0 = *(const __nv_bfloat162*)(vl + off);
            __nv_bfloat162 d1 = *(const __nv_bfloat162*)(vl + off + 2);
            vs[row][c4*4+0] = __bfloat162float(c0.x) + __bfloat162float(d0.x);
            vs[row][c4*4+1] = __bfloat162float(c0.y) + __bfloat162float(d0.y);
            vs[row][c4*4+2] = __bfloat162float(c1.x) + __bfloat162float(d1.x);
            vs[row][c4*4+3] = __bfloat162float(c1.y) + __bfloat162float(d1.y);
        }
        __syncthreads();
#pragma unroll 8
        for (int l = 0; l < 64; l++) {
            float a[4], bb[4];
#pragma unroll
            for (int i = 0; i < 4; i++) a[i] = ks[l][ty*4 + i];
#pragma unroll
            for (int j = 0; j < 4; j++) bb[j] = vs[l][tx*4 + j];
#pragma unroll
            for (int i = 0; i < 4; i++)
#pragma unroll
                for (int j = 0; j < 4; j++) acc[i][j] += a[i] * bb[j];
        }
        if (tid < 64) {
#pragma unroll 8
            for (int l = 0; l < 64; l++) zacc += ks[l][tid];
        }
        __syncthreads();
    }

    float* Gout = g_G + ((size_t)bh * NCH + c) * DH * DH;
#pragma unroll
    for (int i = 0; i < 4; i++)
#pragma unroll
        for (int j = 0; j < 4; j++)
            Gout[(ty*4 + i) * DH + tx*4 + j] = acc[i][j];
    if (tid < 64) g_zc[((size_t)bh * NCH + c) * DH + tid] = zacc;
}

// ---------------- exclusive prefix over chunks; emits S^T as bf16 hi/lo ----------------
__global__ __launch_bounds__(256)
void prefix_kernel()
{
    const int bh = blockIdx.x;
    const int tid = threadIdx.x;
    for (int idx = tid; idx < DH*DH; idx += 256) {
        int d = idx >> 6, e = idx & 63;
        float run = 0.f;
        for (int c = 0; c < NCH; c++) {
            size_t gbase = ((size_t)bh * NCH + c) * DH * DH;
            __nv_bfloat16 hi = __float2bfloat16(run);
            g_ST_hi[gbase + e*DH + d] = hi;
            g_ST_lo[gbase + e*DH + d] = __float2bfloat16(run - __bfloat162float(hi));
            run += g_G[gbase + idx];
        }
    }
    if (tid < DH) {
        float run = 0.f;
        for (int c = 0; c < NCH; c++) {
            size_t o = ((size_t)bh * NCH + c) * DH + tid;
            g_Z[o] = run;
            run += g_zc[o];
        }
    }
}

// ---------------- attention core (HMMA): per (b,h,c), 256x64 tile ----------------
#define AP 144
#define QHI_O 0
#define QLO_O 36864
#define KHI_O 73728
#define KLO_O 82944
#define VTH_O 92160
#define VTL_O 101376
#define STH_O 110592
#define STL_O 119808
#define Z_O   129024
#define ATTN_SMEM (Z_O + 256)

__global__ __launch_bounds__(256, 1)
void attn_core_kernel()
{
    const int c = blockIdx.x, h = blockIdx.y, b = blockIdx.z;
    const int bh = b * HH + h;
    const size_t tokbase = (size_t)bh * LL + c * CH;

    extern __shared__ char sm[];
    const uint32_t sbase = smem_u32(sm);

    const int tid = threadIdx.x;
    const int w = tid >> 5;
    const int lane = tid & 31;
    const int g = lane >> 3, lr = lane & 7;
    const int a_row  = ((g & 1) << 3) + lr;
    const int a_xtra = (g & 2) ? 16 : 0;
    const int b_row  = ((g >> 1) << 3) + lr;
    const int b_xtra = (g & 1) ? 16 : 0;

    // load Q (256x64) hi/lo
    {
        const __nv_bfloat16* qh = g_q_hi + tokbase * DH;
        const __nv_bfloat16* ql = g_q_lo + tokbase * DH;
#pragma unroll
        for (int t = 0; t < 8; t++) {
            int idx = tid + t * 256;
            int row = idx >> 3, c16 = idx & 7;
            *(uint4*)(sm + QHI_O + row*AP + c16*16) = *(const uint4*)(qh + (size_t)row*DH + c16*8);
            *(uint4*)(sm + QLO_O + row*AP + c16*16) = *(const uint4*)(ql + (size_t)row*DH + c16*8);
        }
    }
    // load S^T (64x64) hi/lo + Z
    {
        const size_t stb = ((size_t)bh * NCH + c) * DH * DH;
#pragma unroll
        for (int t = 0; t < 2; t++) {
            int idx = tid + t * 256;
            int row = idx >> 3, c16 = idx & 7;
            *(uint4*)(sm + STH_O + row*AP + c16*16) = *(const uint4*)(g_ST_hi + stb + (size_t)row*DH + c16*8);
            *(uint4*)(sm + STL_O + row*AP + c16*16) = *(const uint4*)(g_ST_lo + stb + (size_t)row*DH + c16*8);
        }
        if (tid < DH) *(float*)(sm + Z_O + tid*4) = g_Z[((size_t)bh * NCH + c) * DH + tid];
    }

    float num[2][8][4];
#pragma unroll
    for (int mi = 0; mi < 2; mi++)
#pragma unroll
        for (int ni = 0; ni < 8; ni++)
#pragma unroll
            for (int e = 0; e < 4; e++) num[mi][ni][e] = 0.f;
    float den[2][2] = {{0.f, 0.f}, {0.f, 0.f}};

    for (int jb = 0; jb < 4; jb++) {
        __syncthreads();   // strip buffers free (also orders Q/ST loads on jb==0)
        // load K strip (64x64) hi/lo
        {
            const __nv_bfloat16* kh = g_k_hi + (tokbase + jb*64) * DH;
            const __nv_bfloat16* kl = g_k_lo + (tokbase + jb*64) * DH;
#pragma unroll
            for (int t = 0; t < 2; t++) {
                int idx = tid + t * 256;
                int row = idx >> 3, c16 = idx & 7;
                *(uint4*)(sm + KHI_O + row*AP + c16*16) = *(const uint4*)(kh + (size_t)row*DH + c16*8);
                *(uint4*)(sm + KLO_O + row*AP + c16*16) = *(const uint4*)(kl + (size_t)row*DH + c16*8);
            }
        }
        // load + transpose V strip: Vt[e][m]
        {
            const __nv_bfloat16* vh = g_v_hi + (tokbase + jb*64) * DH;
            const __nv_bfloat16* vl = g_v_lo + (tokbase + jb*64) * DH;
#pragma unroll
            for (int t = 0; t < 4; t++) {
                int s = tid + t * 256;
                int m = s >> 4, e = (s & 15) * 4;
                __nv_bfloat162 h0 = *(const __nv_bfloat162*)(vh + (size_t)m*DH + e);
                __nv_bfloat162 h1 = *(const __nv_bfloat162*)(vh + (size_t)m*DH + e + 2);
                __nv_bfloat162 l0 = *(const __nv_bfloat162*)(vl + (size_t)m*DH + e);
                __nv_bfloat162 l1 = *(const __nv_bfloat162*)(vl + (size_t)m*DH + e + 2);
                *(__nv_bfloat16*)(sm + VTH_O + (e+0)*AP + m*2) = h0.x;
                *(__nv_bfloat16*)(sm + VTH_O + (e+1)*AP + m*2) = h0.y;
                *(__nv_bfloat16*)(sm + VTH_O + (e+2)*AP + m*2) = h1.x;
                *(__nv_bfloat16*)(sm + VTH_O + (e+3)*AP + m*2) = h1.y;
                *(__nv_bfloat16*)(sm + VTL_O + (e+0)*AP + m*2) = l0.x;
                *(__nv_bfloat16*)(sm + VTL_O + (e+1)*AP + m*2) = l0.y;
                *(__nv_bfloat16*)(sm + VTL_O + (e+2)*AP + m*2) = l1.x;
                *(__nv_bfloat16*)(sm + VTL_O + (e+3)*AP + m*2) = l1.y;
            }
        }
        __syncthreads();

        // GEMM1: P = Q * Kstrip^T  (warp: 32x64, k=64)
        float pacc[2][8][4];
#pragma unroll
        for (int mi = 0; mi < 2; mi++)
#pragma unroll
            for (int ni = 0; ni < 8; ni++)
#pragma unroll
                for (int e = 0; e < 4; e++) pacc[mi][ni][e] = 0.f;

#pragma unroll
        for (int t = 0; t < 4; t++) {
            uint32_t kbh[16], kbl[16];
#pragma unroll
            for (int np = 0; np < 4; np++) {
                uint32_t off = (uint32_t)((np*16 + b_row)*AP + t*32 + b_xtra);
                ldmx4(kbh + np*4, sbase + KHI_O + off);
                ldmx4(kbl + np*4, sbase + KLO_O + off);
            }
#pragma unroll
            for (int mi = 0; mi < 2; mi++) {
                uint32_t ah[4], al[4];
                uint32_t off = (uint32_t)((w*32 + mi*16 + a_row)*AP + t*32 + a_xtra);
                ldmx4(ah, sbase + QHI_O + off);
                ldmx4(al, sbase + QLO_O + off);
#pragma unroll
                for (int ni = 0; ni < 8; ni++) {
                    const uint32_t* bh = &kbh[(ni >> 1)*4 + (ni & 1)*2];
                    const uint32_t* bl = &kbl[(ni >> 1)*4 + (ni & 1)*2];
                    mma_bf16(pacc[mi][ni], ah, bh);
                    mma_bf16(pacc[mi][ni], ah, bl);
                    mma_bf16(pacc[mi][ni], al, bh);
                }
            }
        }

        // causal mask + den partials
#pragma unroll
        for (int mi = 0; mi < 2; mi++)
#pragma unroll
            for (int ni = 0; ni < 8; ni++)
#pragma unroll
                for (int e = 0; e < 4; e++) {
                    int row = w*32 + mi*16 + (lane >> 2) + (e >> 1)*8;
                    int col = jb*64 + ni*8 + (lane & 3)*2 + (e & 1);
                    if (col > row) pacc[mi][ni][e] = 0.f;
                    else           den[mi][e >> 1] += pacc[mi][ni][e];
                }

        // GEMM2: num += P * Vstrip  (k = strip token dim, via Vt)
#pragma unroll
        for (int t = 0; t < 4; t++) {
            uint32_t vbh[16], vbl[16];
#pragma unroll
            for (int np = 0; np < 4; np++) {
                uint32_t off = (uint32_t)((np*16 + b_row)*AP + t*32 + b_xtra);
                ldmx4(vbh + np*4, sbase + VTH_O + off);
                ldmx4(vbl + np*4, sbase + VTL_O + off);
            }
#pragma unroll
            for (int mi = 0; mi < 2; mi++) {
                // acc->A-frag identity: tile 2t & 2t+1 supply k16 tile t
                uint32_t ph[4], pl[4];
                split2(pacc[mi][2*t][0],   pacc[mi][2*t][1],   ph[0], pl[0]);
                split2(pacc[mi][2*t][2],   pacc[mi][2*t][3],   ph[1], pl[1]);
                split2(pacc[mi][2*t+1][0], pacc[mi][2*t+1][1], ph[2], pl[2]);
                split2(pacc[mi][2*t+1][2], pacc[mi][2*t+1][3], ph[3], pl[3]);
#pragma unroll
                for (int ni = 0; ni < 8; ni++) {
                    const uint32_t* bh = &vbh[(ni >> 1)*4 + (ni & 1)*2];
                    const uint32_t* bl = &vbl[(ni >> 1)*4 + (ni & 1)*2];
                    mma_bf16(num[mi][ni], ph, bh);
                    mma_bf16(num[mi][ni], ph, bl);
                    mma_bf16(num[mi][ni], pl, bh);
                }
            }
        }
    }

    // inter-chunk: num += Q * S (B = S^T)
#pragma unroll
    for (int t = 0; t < 4; t++) {
        uint32_t sbh[16], sbl[16];
#pragma unroll
        for (int np = 0; np < 4; np++) {
            uint32_t off = (uint32_t)((np*16 + b_row)*AP + t*32 + b_xtra);
            ldmx4(sbh + np*4, sbase + STH_O + off);
            ldmx4(sbl + np*4, sbase + STL_O + off);
        }
#pragma unroll
        for (int mi = 0; mi < 2; mi++) {
            uint32_t ah[4], al[4];
            uint32_t off = (uint32_t)((w*32 + mi*16 + a_row)*AP + t*32 + a_xtra);
            ldmx4(ah, sbase + QHI_O + off);
            ldmx4(al, sbase + QLO_O + off);
#pragma unroll
            for (int ni = 0; ni < 8; ni++) {
                const uint32_t* bh = &sbh[(ni >> 1)*4 + (ni & 1)*2];
                const uint32_t* bl = &sbl[(ni >> 1)*4 + (ni & 1)*2];
                mma_bf16(num[mi][ni], ah, bh);
                mma_bf16(num[mi][ni], ah, bl);
                mma_bf16(num[mi][ni], al, bh);
            }
        }
    }

    // den: quad reduce, then + q.Z
#pragma unroll
    for (int mi = 0; mi < 2; mi++)
#pragma unroll
        for (int hf = 0; hf < 2; hf++) {
            float d = den[mi][hf];
            d += __shfl_xor_sync(0xffffffffu, d, 1);
            d += __shfl_xor_sync(0xffffffffu, d, 2);
            int row = w*32 + mi*16 + (lane >> 2) + hf*8;
            float qz = 0.f;
            const char* qrh = sm + QHI_O + row*AP;
            const char* qrl = sm + QLO_O + row*AP;
#pragma unroll
            for (int dd = 0; dd < 32; dd++) {
                __nv_bfloat162 qh2 = *(const __nv_bfloat162*)(qrh + dd*4);
                __nv_bfloat162 ql2 = *(const __nv_bfloat162*)(qrl + dd*4);
                float2 z2 = *(const float2*)(sm + Z_O + dd*8);
                qz += (__bfloat162float(qh2.x) + __bfloat162float(ql2.x)) * z2.x
                    + (__bfloat162float(qh2.y) + __bfloat162float(ql2.y)) * z2.y;
            }
            den[mi][hf] = d + qz;
        }

    // divide + split-bf16 store to g_att
    const size_t mbase = (size_t)(b * LL + c * CH);
#pragma unroll
    for (int mi = 0; mi < 2; mi++)
#pragma unroll
        for (int hf = 0; hf < 2; hf++) {
            int row = w*32 + mi*16 + (lane >> 2) + hf*8;
            float inv = 1.f / fmaxf(den[mi][hf], 1e-6f);
            size_t ob = (mbase + row) * EE + h * DH;
#pragma unroll
            for (int ni = 0; ni < 8; ni++) {
                int e = ni*8 + (lane & 3)*2;
                float v0 = num[mi][ni][hf*2 + 0] * inv;
                float v1 = num[mi][ni][hf*2 + 1] * inv;
                uint32_t hi, lo;
                split2(v0, v1, hi, lo);
                *(uint32_t*)(g_att_hi + ob + e) = hi;
                *(uint32_t*)(g_att_lo + ob + e) = lo;
            }
        }
}

// ---------------- launch ----------------
extern "C" void kernel_launch(void* const* d_in, const int* in_sizes, int n_in,
                              void* d_out, int out_size)
{
    const float* x    = (const float*)d_in[0];   // [B, L, E]
    const float* Wqkv = (const float*)d_in[1];   // [3E, E]
    const float* Wout = (const float*)d_in[2];   // [E, E]
    float* out = (float*)d_out;                  // [B, L, E]

    cudaFuncSetAttribute(attn_core_kernel,
                         cudaFuncAttributeMaxDynamicSharedMemorySize, ATTN_SMEM);
    const int gemm_smem = 2 * STAGE2;  // 81920
    cudaFuncSetAttribute(hmma_gemm_kernel<0>,
                         cudaFuncAttributeMaxDynamicSharedMemorySize, gemm_smem);
    cudaFuncSetAttribute(hmma_gemm_kernel<1>,
                         cudaFuncAttributeMaxDynamicSharedMemorySize, gemm_smem);

    // 0) split-bf16 conversion of inputs
    convert_kernel<0><<<(M1*EE/4 + 255)/256, 256>>>(x, M1*EE/4);
    convert_kernel<1><<<(NQKV*EE/4 + 255)/256, 256>>>(Wqkv, NQKV*EE/4);
    convert_kernel<2><<<(EE*EE/4 + 255)/256, 256>>>(Wout, EE*EE/4);

    // 1) QKV GEMM + feature-map -> bf16 hi/lo q/k/v
    {
        dim3 grid(NQKV/128, M1/128);  // (24, 64)
        hmma_gemm_kernel<0><<<grid, 256, gemm_smem>>>(nullptr);
    }
    // 2) per-chunk Gram matrices
    {
        dim3 grid(NCH, HH, BB);
        chunk_kv_kernel<<<grid, 256>>>();
    }
    // 3) exclusive prefix (emits S^T bf16 hi/lo + Z)
    prefix_kernel<<<BB*HH, 256>>>();
    // 4) attention core (HMMA, writes split-bf16 g_att)
    {
        dim3 grid(NCH, HH, BB);
        attn_core_kernel<<<grid, 256, ATTN_SMEM>>>();
    }
    // 5) output GEMM: out = att @ Wout^T
    {
        dim3 grid(EE/128, M1/128);    // (8, 64)
        hmma_gemm_kernel<1><<<grid, 256, gemm_smem>>>(out);
    }
}

// round 8
// speedup vs baseline: 2.2170x; 1.0007x over previous
#include <cuda_runtime.h>
#include <cuda_bf16.h>
#include <math.h>
#include <stdint.h>

#define BB 2
#define LL 4096
#define EE 1024
#define HH 16
#define DH 64
#define CH 256
#define NCH 16
#define M1 (BB*LL)      // 8192
#define NQKV (3*EE)     // 3072

// ---------------- scratch (static device globals; no allocation) ----------------
__device__ __align__(16) __nv_bfloat16 g_xhi[(size_t)M1*EE],   g_xlo[(size_t)M1*EE];
__device__ __align__(16) __nv_bfloat16 g_wqkv_hi[(size_t)NQKV*EE], g_wqkv_lo[(size_t)NQKV*EE];
__device__ __align__(16) __nv_bfloat16 g_wout_hi[(size_t)EE*EE],   g_wout_lo[(size_t)EE*EE];
__device__ __align__(16) __nv_bfloat16 g_att_hi[(size_t)M1*EE],    g_att_lo[(size_t)M1*EE];

__device__ __align__(16) __nv_bfloat16 g_q_hi[(size_t)BB*HH*LL*DH], g_q_lo[(size_t)BB*HH*LL*DH];
__device__ __align__(16) __nv_bfloat16 g_k_hi[(size_t)BB*HH*LL*DH], g_k_lo[(size_t)BB*HH*LL*DH];
__device__ __align__(16) __nv_bfloat16 g_v_hi[(size_t)BB*HH*LL*DH], g_v_lo[(size_t)BB*HH*LL*DH];

__device__ float g_G[(size_t)BB*HH*NCH*DH*DH];
__device__ __align__(16) __nv_bfloat16 g_ST_hi[(size_t)BB*HH*NCH*DH*DH], g_ST_lo[(size_t)BB*HH*NCH*DH*DH];
__device__ float g_zc[(size_t)BB*HH*NCH*DH];
__device__ float g_Z[(size_t)BB*HH*NCH*DH];

// ---------------- helpers ----------------
__device__ __forceinline__ uint32_t smem_u32(const void* p) {
    uint32_t a;
    asm("{ .reg .u64 t; cvta.to.shared.u64 t, %1; cvt.u32.u64 %0, t; }" : "=r"(a) : "l"(p));
    return a;
}
__device__ __forceinline__ void ldmx4(uint32_t* r, uint32_t a) {
    asm volatile("ldmatrix.sync.aligned.m8n8.x4.shared.b16 {%0,%1,%2,%3}, [%4];"
        : "=r"(r[0]), "=r"(r[1]), "=r"(r[2]), "=r"(r[3]) : "r"(a));
}
__device__ __forceinline__ void mma_bf16(float* d, const uint32_t* a, const uint32_t* b) {
    asm volatile(
        "mma.sync.aligned.m16n8k16.row.col.f32.bf16.bf16.f32 "
        "{%0,%1,%2,%3}, {%4,%5,%6,%7}, {%8,%9}, {%0,%1,%2,%3};"
        : "+f"(d[0]), "+f"(d[1]), "+f"(d[2]), "+f"(d[3])
        : "r"(a[0]), "r"(a[1]), "r"(a[2]), "r"(a[3]), "r"(b[0]), "r"(b[1]));
}
__device__ __forceinline__ uint32_t pack_bf2(__nv_bfloat16 a, __nv_bfloat16 b) {
    __nv_bfloat162 t(a, b);
    return *(uint32_t*)&t;
}
// split two fp32 into packed (hi, lo) bf16x2
__device__ __forceinline__ void split2(float a, float b, uint32_t& hi, uint32_t& lo) {
    __nv_bfloat16 ha = __float2bfloat16(a), hb = __float2bfloat16(b);
    __nv_bfloat16 la = __float2bfloat16(a - __bfloat162float(ha));
    __nv_bfloat16 lb = __float2bfloat16(b - __bfloat162float(hb));
    hi = pack_bf2(ha, hb);
    lo = pack_bf2(la, lb);
}

#define CP_ASYNC16(s, g) \
    asm volatile("cp.async.cg.shared.global [%0], [%1], 16;" :: "r"(s), "l"(g))
#define CP_COMMIT() asm volatile("cp.async.commit_group;")
#define CP_WAIT1()  asm volatile("cp.async.wait_group 1;")
#define CP_WAIT0()  asm volatile("cp.async.wait_group 0;")

// ---------------- fp32 -> (hi,lo) bf16 split converter ----------------
template<int W>
__global__ __launch_bounds__(256)
void convert_kernel(const float* __restrict__ src, int n4)
{
    __nv_bfloat16 *hi, *lo;
    if (W == 0)      { hi = g_xhi;     lo = g_xlo; }
    else if (W == 1) { hi = g_wqkv_hi; lo = g_wqkv_lo; }
    else             { hi = g_wout_hi; lo = g_wout_lo; }
    int i = blockIdx.x * 256 + threadIdx.x;
    if (i >= n4) return;
    float4 v = ((const float4*)src)[i];
    float a[4] = {v.x, v.y, v.z, v.w};
    __nv_bfloat16 h[4], l[4];
#pragma unroll
    for (int j = 0; j < 4; j++) {
        h[j] = __float2bfloat16(a[j]);
        l[j] = __float2bfloat16(a[j] - __bfloat162float(h[j]));
    }
    ((__nv_bfloat162*)hi)[i*2 + 0] = __nv_bfloat162(h[0], h[1]);
    ((__nv_bfloat162*)hi)[i*2 + 1] = __nv_bfloat162(h[2], h[3]);
    ((__nv_bfloat162*)lo)[i*2 + 0] = __nv_bfloat162(l[0], l[1]);
    ((__nv_bfloat162*)lo)[i*2 + 1] = __nv_bfloat162(l[2], l[3]);
}

// ---------------- HMMA GEMM, cp.async double-buffered, BK=32 ----------------
// C[M,N] = A[M,K] * B[N,K]^T = hi*hi + hi*lo + lo*hi, fp32 accumulate.
// Term-major MMA ordering: 4 independent MMAs between accumulator reuses.
#define P2 80
#define TILE2 (128*P2)     // 10240
#define STAGE2 (4*TILE2)   // 40960

template<int MODE>
__global__ __launch_bounds__(256, 2)
void hmma_gemm_kernel(float* __restrict__ C)
{
    const __nv_bfloat16* __restrict__ Ahi = (MODE == 0) ? g_xhi : g_att_hi;
    const __nv_bfloat16* __restrict__ Alo = (MODE == 0) ? g_xlo : g_att_lo;
    const __nv_bfloat16* __restrict__ Bhi = (MODE == 0) ? g_wqkv_hi : g_wout_hi;
    const __nv_bfloat16* __restrict__ Blo = (MODE == 0) ? g_wqkv_lo : g_wout_lo;

    const int m0 = blockIdx.y * 128;
    const int n0 = blockIdx.x * 128;
    const int tid = threadIdx.x;
    const int wid = tid >> 5;
    const int lane = tid & 31;
    const int wm = (wid >> 2) * 64;
    const int wn = (wid & 3) * 32;

    extern __shared__ char smc[];
    const uint32_t base = smem_u32(smc);

    float acc[4][4][4];
#pragma unroll
    for (int a = 0; a < 4; a++)
#pragma unroll
        for (int b = 0; b < 4; b++)
#pragma unroll
            for (int c = 0; c < 4; c++) acc[a][b][c] = 0.f;

    const int g = lane >> 3, lr = lane & 7;
    const int a_row  = ((g & 1) << 3) + lr;
    const int a_xtra = (g & 2) ? 16 : 0;
    const int b_row  = ((g >> 1) << 3) + lr;
    const int b_xtra = (g & 1) ? 16 : 0;

    auto prefetch = [&](int kc, int stg) {
        const int kb = kc * 32;
        const uint32_t sb = base + stg * STAGE2;
#pragma unroll
        for (int i = 0; i < 2; i++) {
            int s = tid + i * 256;          // 0..511
            int row = s >> 2, c16 = s & 3;
            uint32_t so = (uint32_t)(row * P2 + c16 * 16);
            size_t ga = (size_t)(m0 + row) * EE + kb + c16 * 8;
            size_t gb = (size_t)(n0 + row) * EE + kb + c16 * 8;
            CP_ASYNC16(sb + so,           __cvta_generic_to_global(Ahi + ga));
            CP_ASYNC16(sb + TILE2 + so,   __cvta_generic_to_global(Alo + ga));
            CP_ASYNC16(sb + 2*TILE2 + so, __cvta_generic_to_global(Bhi + gb));
            CP_ASYNC16(sb + 3*TILE2 + so, __cvta_generic_to_global(Blo + gb));
        }
    };

    prefetch(0, 0); CP_COMMIT();

    for (int kc = 0; kc < 32; kc++) {
        const int stg = kc & 1;
        if (kc + 1 < 32) { prefetch(kc + 1, stg ^ 1); CP_COMMIT(); CP_WAIT1(); }
        else             { CP_WAIT0(); }
        __syncthreads();

        const uint32_t sb = base + stg * STAGE2;
#pragma unroll
        for (int t = 0; t < 2; t++) {
            uint32_t bfh[8], bfl[8];
#pragma unroll
            for (int np = 0; np < 2; np++) {
                uint32_t off = (uint32_t)((wn + np*16 + b_row) * P2 + t*32 + b_xtra);
                ldmx4(bfh + np*4, sb + 2*TILE2 + off);
                ldmx4(bfl + np*4, sb + 3*TILE2 + off);
            }
#pragma unroll
            for (int mi = 0; mi < 4; mi++) {
                uint32_t afh[4], afl[4];
                uint32_t off = (uint32_t)((wm + mi*16 + a_row) * P2 + t*32 + a_xtra);
                ldmx4(afh, sb + off);
                ldmx4(afl, sb + TILE2 + off);
                // term-major: all ni of hi*hi, then hi*lo, then lo*hi
#pragma unroll
                for (int ni = 0; ni < 4; ni++)
                    mma_bf16(acc[mi][ni], afh, &bfh[(ni >> 1)*4 + (ni & 1)*2]);
#pragma unroll
                for (int ni = 0; ni < 4; ni++)
                    mma_bf16(acc[mi][ni], afh, &bfl[(ni >> 1)*4 + (ni & 1)*2]);
#pragma unroll
                for (int ni = 0; ni < 4; ni++)
                    mma_bf16(acc[mi][ni], afl, &bfh[(ni >> 1)*4 + (ni & 1)*2]);
            }
        }
        __syncthreads();
    }

    // epilogue
#pragma unroll
    for (int mi = 0; mi < 4; mi++) {
        int mrow = m0 + wm + mi*16 + (lane >> 2);
#pragma unroll
        for (int half = 0; half < 2; half++) {
            int m = mrow + half * 8;
#pragma unroll
            for (int ni = 0; ni < 4; ni++) {
                int n = n0 + wn + ni*8 + (lane & 3)*2;
                float v0 = acc[mi][ni][half*2 + 0];
                float v1 = acc[mi][ni][half*2 + 1];
                if (MODE == 1) {
                    *(float2*)(C + (size_t)m * EE + n) = make_float2(v0, v1);
                } else {
                    int s = n >> 10, h = (n >> 6) & 15, d = n & 63;
                    int bidx = m >> 12, l = m & 4095;
                    float r0, r1;
                    if (s == 0) {
                        r0 = (v0 > 0.f ? v0 + 1.f : expf(v0)) * 0.125f;
                        r1 = (v1 > 0.f ? v1 + 1.f : expf(v1)) * 0.125f;
                    } else if (s == 1) {
                        r0 = (v0 > 0.f ? v0 + 1.f : expf(v0));
                        r1 = (v1 > 0.f ? v1 + 1.f : expf(v1));
                    } else {
                        r0 = v0; r1 = v1;
                    }
                    uint32_t hi, lo;
                    split2(r0, r1, hi, lo);
                    __nv_bfloat16* dh = (s == 0) ? g_q_hi : (s == 1) ? g_k_hi : g_v_hi;
                    __nv_bfloat16* dl = (s == 0) ? g_q_lo : (s == 1) ? g_k_lo : g_v_lo;
                    size_t off = ((size_t)(bidx*HH + h) * LL + l) * DH + d;
                    *(uint32_t*)(dh + off) = hi;
                    *(uint32_t*)(dl + off) = lo;
                }
            }
        }
    }
}

// ---------------- per-chunk Gram: G = K_c^T V_c  (64x64), z = sum K_c ----------------
__global__ __launch_bounds__(256)
void chunk_kv_kernel()
{
    const int c = blockIdx.x, h = blockIdx.y, b = blockIdx.z;
    const int bh = b * HH + h;
    const size_t tokbase = ((size_t)bh * LL + c * CH) * DH;
    const __nv_bfloat16* kh = g_k_hi + tokbase;
    const __nv_bfloat16* kl = g_k_lo + tokbase;
    const __nv_bfloat16* vh = g_v_hi + tokbase;
    const __nv_bfloat16* vl = g_v_lo + tokbase;

    __shared__ float ks[64][65];
    __shared__ float vs[64][65];

    const int tid = threadIdx.x;
    const int tx = tid & 15, ty = tid >> 4;

    float acc[4][4];
#pragma unroll
    for (int i = 0; i < 4; i++)
#pragma unroll
        for (int j = 0; j < 4; j++) acc[i][j] = 0.f;
    float zacc = 0.f;

    for (int lt = 0; lt < 4; lt++) {
#pragma unroll
        for (int t = 0; t < 4; t++) {
            int idx = tid + t * 256;
            int row = idx >> 4, c4 = idx & 15;
            size_t off = (size_t)(lt*64 + row) * DH + c4 * 4;
            __nv_bfloat162 a0 = *(const __nv_bfloat162*)(kh + off);
            __nv_bfloat162 a1 = *(const __nv_bfloat162*)(kh + off + 2);
            __nv_bfloat162 b0 = *(const __nv_bfloat162*)(kl + off);
            __nv_bfloat162 b1 = *(const __nv_bfloat162*)(kl + off + 2);
            ks[row][c4*4+0] = __bfloat162float(a0.x) + __bfloat162float(b0.x);
            ks[row][c4*4+1] = __bfloat162float(a0.y) + __bfloat162float(b0.y);
            ks[row][c4*4+2] = __bfloat162float(a1.x) + __bfloat162float(b1.x);
            ks[row][c4*4+3] = __bfloat162float(a1.y) + __bfloat162float(b1.y);
            __nv_bfloat162 c0 = *(const __nv_bfloat162*)(vh + off);
            __nv_bfloat162 c1 = *(const __nv_bfloat162*)(vh + off + 2);
            __nv_bfloat162 d0 = *(const __nv_bfloat162*)(vl + off);
            __nv_bfloat162 d1 = *(const __nv_bfloat162*)(vl + off + 2);
            vs[row][c4*4+0] = __bfloat162float(c0.x) + __bfloat162float(d0.x);
            vs[row][c4*4+1] = __bfloat162float(c0.y) + __bfloat162float(d0.y);
            vs[row][c4*4+2] = __bfloat162float(c1.x) + __bfloat162float(d1.x);
            vs[row][c4*4+3] = __bfloat162float(c1.y) + __bfloat162float(d1.y);
        }
        __syncthreads();
#pragma unroll 8
        for (int l = 0; l < 64; l++) {
            float a[4], bb[4];
#pragma unroll
            for (int i = 0; i < 4; i++) a[i] = ks[l][ty*4 + i];
#pragma unroll
            for (int j = 0; j < 4; j++) bb[j] = vs[l][tx*4 + j];
#pragma unroll
            for (int i = 0; i < 4; i++)
#pragma unroll
                for (int j = 0; j < 4; j++) acc[i][j] += a[i] * bb[j];
        }
        if (tid < 64) {
#pragma unroll 8
            for (int l = 0; l < 64; l++) zacc += ks[l][tid];
        }
        __syncthreads();
    }

    float* Gout = g_G + ((size_t)bh * NCH + c) * DH * DH;
#pragma unroll
    for (int i = 0; i < 4; i++)
#pragma unroll
        for (int j = 0; j < 4; j++)
            Gout[(ty*4 + i) * DH + tx*4 + j] = acc[i][j];
    if (tid < 64) g_zc[((size_t)bh * NCH + c) * DH + tid] = zacc;
}

// ---------------- exclusive prefix over chunks; emits S^T as bf16 hi/lo ----------------
__global__ __launch_bounds__(256)
void prefix_kernel()
{
    const int bh = blockIdx.x;
    const int tid = threadIdx.x;
    for (int idx = tid; idx < DH*DH; idx += 256) {
        int d = idx >> 6, e = idx & 63;
        float run = 0.f;
        for (int c = 0; c < NCH; c++) {
            size_t gbase = ((size_t)bh * NCH + c) * DH * DH;
            __nv_bfloat16 hi = __float2bfloat16(run);
            g_ST_hi[gbase + e*DH + d] = hi;
            g_ST_lo[gbase + e*DH + d] = __float2bfloat16(run - __bfloat162float(hi));
            run += g_G[gbase + idx];
        }
    }
    if (tid < DH) {
        float run = 0.f;
        for (int c = 0; c < NCH; c++) {
            size_t o = ((size_t)bh * NCH + c) * DH + tid;
            g_Z[o] = run;
            run += g_zc[o];
        }
    }
}

// ---------------- attention core (HMMA): per (b,h,c), 256x64 tile ----------------
#define AP 144
#define QHI_O 0
#define QLO_O 36864
#define KHI_O 73728
#define KLO_O 82944
#define VTH_O 92160
#define VTL_O 101376
#define STH_O 110592
#define STL_O 119808
#define Z_O   129024
#define ATTN_SMEM (Z_O + 256)

__global__ __launch_bounds__(256, 1)
void attn_core_kernel()
{
    const int c = blockIdx.x, h = blockIdx.y, b = blockIdx.z;
    const int bh = b * HH + h;
    const size_t tokbase = (size_t)bh * LL + c * CH;

    extern __shared__ char sm[];
    const uint32_t sbase = smem_u32(sm);

    const int tid = threadIdx.x;
    const int w = tid >> 5;
    const int lane = tid & 31;
    const int g = lane >> 3, lr = lane & 7;
    const int a_row  = ((g & 1) << 3) + lr;
    const int a_xtra = (g & 2) ? 16 : 0;
    const int b_row  = ((g >> 1) << 3) + lr;
    const int b_xtra = (g & 1) ? 16 : 0;

    // load Q (256x64) hi/lo
    {
        const __nv_bfloat16* qh = g_q_hi + tokbase * DH;
        const __nv_bfloat16* ql = g_q_lo + tokbase * DH;
#pragma unroll
        for (int t = 0; t < 8; t++) {
            int idx = tid + t * 256;
            int row = idx >> 3, c16 = idx & 7;
            *(uint4*)(sm + QHI_O + row*AP + c16*16) = *(const uint4*)(qh + (size_t)row*DH + c16*8);
            *(uint4*)(sm + QLO_O + row*AP + c16*16) = *(const uint4*)(ql + (size_t)row*DH + c16*8);
        }
    }
    // load S^T (64x64) hi/lo + Z
    {
        const size_t stb = ((size_t)bh * NCH + c) * DH * DH;
#pragma unroll
        for (int t = 0; t < 2; t++) {
            int idx = tid + t * 256;
            int row = idx >> 3, c16 = idx & 7;
            *(uint4*)(sm + STH_O + row*AP + c16*16) = *(const uint4*)(g_ST_hi + stb + (size_t)row*DH + c16*8);
            *(uint4*)(sm + STL_O + row*AP + c16*16) = *(const uint4*)(g_ST_lo + stb + (size_t)row*DH + c16*8);
        }
        if (tid < DH) *(float*)(sm + Z_O + tid*4) = g_Z[((size_t)bh * NCH + c) * DH + tid];
    }

    float num[2][8][4];
#pragma unroll
    for (int mi = 0; mi < 2; mi++)
#pragma unroll
        for (int ni = 0; ni < 8; ni++)
#pragma unroll
            for (int e = 0; e < 4; e++) num[mi][ni][e] = 0.f;
    float den[2][2] = {{0.f, 0.f}, {0.f, 0.f}};

    for (int jb = 0; jb < 4; jb++) {
        __syncthreads();   // strip buffers free (also orders Q/ST loads on jb==0)
        // load K strip (64x64) hi/lo
        {
            const __nv_bfloat16* kh = g_k_hi + (tokbase + jb*64) * DH;
            const __nv_bfloat16* kl = g_k_lo + (tokbase + jb*64) * DH;
#pragma unroll
            for (int t = 0; t < 2; t++) {
                int idx = tid + t * 256;
                int row = idx >> 3, c16 = idx & 7;
                *(uint4*)(sm + KHI_O + row*AP + c16*16) = *(const uint4*)(kh + (size_t)row*DH + c16*8);
                *(uint4*)(sm + KLO_O + row*AP + c16*16) = *(const uint4*)(kl + (size_t)row*DH + c16*8);
            }
        }
        // load + transpose V strip: Vt[e][m]
        {
            const __nv_bfloat16* vh = g_v_hi + (tokbase + jb*64) * DH;
            const __nv_bfloat16* vl = g_v_lo + (tokbase + jb*64) * DH;
#pragma unroll
            for (int t = 0; t < 4; t++) {
                int s = tid + t * 256;
                int m = s >> 4, e = (s & 15) * 4;
                __nv_bfloat162 h0 = *(const __nv_bfloat162*)(vh + (size_t)m*DH + e);
                __nv_bfloat162 h1 = *(const __nv_bfloat162*)(vh + (size_t)m*DH + e + 2);
                __nv_bfloat162 l0 = *(const __nv_bfloat162*)(vl + (size_t)m*DH + e);
                __nv_bfloat162 l1 = *(const __nv_bfloat162*)(vl + (size_t)m*DH + e + 2);
                *(__nv_bfloat16*)(sm + VTH_O + (e+0)*AP + m*2) = h0.x;
                *(__nv_bfloat16*)(sm + VTH_O + (e+1)*AP + m*2) = h0.y;
                *(__nv_bfloat16*)(sm + VTH_O + (e+2)*AP + m*2) = h1.x;
                *(__nv_bfloat16*)(sm + VTH_O + (e+3)*AP + m*2) = h1.y;
                *(__nv_bfloat16*)(sm + VTL_O + (e+0)*AP + m*2) = l0.x;
                *(__nv_bfloat16*)(sm + VTL_O + (e+1)*AP + m*2) = l0.y;
                *(__nv_bfloat16*)(sm + VTL_O + (e+2)*AP + m*2) = l1.x;
                *(__nv_bfloat16*)(sm + VTL_O + (e+3)*AP + m*2) = l1.y;
            }
        }
        __syncthreads();

        // GEMM1: P = Q * Kstrip^T  (warp: 32x64, k=64)
        float pacc[2][8][4];
#pragma unroll
        for (int mi = 0; mi < 2; mi++)
#pragma unroll
            for (int ni = 0; ni < 8; ni++)
#pragma unroll
                for (int e = 0; e < 4; e++) pacc[mi][ni][e] = 0.f;

#pragma unroll
        for (int t = 0; t < 4; t++) {
            uint32_t kbh[16], kbl[16];
#pragma unroll
            for (int np = 0; np < 4; np++) {
                uint32_t off = (uint32_t)((np*16 + b_row)*AP + t*32 + b_xtra);
                ldmx4(kbh + np*4, sbase + KHI_O + off);
                ldmx4(kbl + np*4, sbase + KLO_O + off);
            }
#pragma unroll
            for (int mi = 0; mi < 2; mi++) {
                uint32_t ah[4], al[4];
                uint32_t off = (uint32_t)((w*32 + mi*16 + a_row)*AP + t*32 + a_xtra);
                ldmx4(ah, sbase + QHI_O + off);
                ldmx4(al, sbase + QLO_O + off);
                // term-major over ni (distance-8 dependency)
#pragma unroll
                for (int ni = 0; ni < 8; ni++)
                    mma_bf16(pacc[mi][ni], ah, &kbh[(ni >> 1)*4 + (ni & 1)*2]);
#pragma unroll
                for (int ni = 0; ni < 8; ni++)
                    mma_bf16(pacc[mi][ni], ah, &kbl[(ni >> 1)*4 + (ni & 1)*2]);
#pragma unroll
                for (int ni = 0; ni < 8; ni++)
                    mma_bf16(pacc[mi][ni], al, &kbh[(ni >> 1)*4 + (ni & 1)*2]);
            }
        }

        // causal mask + den partials
#pragma unroll
        for (int mi = 0; mi < 2; mi++)
#pragma unroll
            for (int ni = 0; ni < 8; ni++)
#pragma unroll
                for (int e = 0; e < 4; e++) {
                    int row = w*32 + mi*16 + (lane >> 2) + (e >> 1)*8;
                    int col = jb*64 + ni*8 + (lane & 3)*2 + (e & 1);
                    if (col > row) pacc[mi][ni][e] = 0.f;
                    else           den[mi][e >> 1] += pacc[mi][ni][e];
                }

        // GEMM2: num += P * Vstrip  (k = strip token dim, via Vt)
#pragma unroll
        for (int t = 0; t < 4; t++) {
            uint32_t vbh[16], vbl[16];
#pragma unroll
            for (int np = 0; np < 4; np++) {
                uint32_t off = (uint32_t)((np*16 + b_row)*AP + t*32 + b_xtra);
                ldmx4(vbh + np*4, sbase + VTH_O + off);
                ldmx4(vbl + np*4, sbase + VTL_O + off);
            }
#pragma unroll
            for (int mi = 0; mi < 2; mi++) {
                // acc->A-frag identity: tile 2t & 2t+1 supply k16 tile t
                uint32_t ph[4], pl[4];
                split2(pacc[mi][2*t][0],   pacc[mi][2*t][1],   ph[0], pl[0]);
                split2(pacc[mi][2*t][2],   pacc[mi][2*t][3],   ph[1], pl[1]);
                split2(pacc[mi][2*t+1][0], pacc[mi][2*t+1][1], ph[2], pl[2]);
                split2(pacc[mi][2*t+1][2], pacc[mi][2*t+1][3], ph[3], pl[3]);
                // term-major over ni
#pragma unroll
                for (int ni = 0; ni < 8; ni++)
                    mma_bf16(num[mi][ni], ph, &vbh[(ni >> 1)*4 + (ni & 1)*2]);
#pragma unroll
                for (int ni = 0; ni < 8; ni++)
                    mma_bf16(num[mi][ni], ph, &vbl[(ni >> 1)*4 + (ni & 1)*2]);
#pragma unroll
                for (int ni = 0; ni < 8; ni++)
                    mma_bf16(num[mi][ni], pl, &vbh[(ni >> 1)*4 + (ni & 1)*2]);
            }
        }
    }

    // inter-chunk: num += Q * S (B = S^T)
#pragma unroll
    for (int t = 0; t < 4; t++) {
        uint32_t sbh[16], sbl[16];
#pragma unroll
        for (int np = 0; np < 4; np++) {
            uint32_t off = (uint32_t)((np*16 + b_row)*AP + t*32 + b_xtra);
            ldmx4(sbh + np*4, sbase + STH_O + off);
            ldmx4(sbl + np*4, sbase + STL_O + off);
        }
#pragma unroll
        for (int mi = 0; mi < 2; mi++) {
            uint32_t ah[4], al[4];
            uint32_t off = (uint32_t)((w*32 + mi*16 + a_row)*AP + t*32 + a_xtra);
            ldmx4(ah, sbase + QHI_O + off);
            ldmx4(al, sbase + QLO_O + off);
#pragma unroll
            for (int ni = 0; ni < 8; ni++)
                mma_bf16(num[mi][ni], ah, &sbh[(ni >> 1)*4 + (ni & 1)*2]);
#pragma unroll
            for (int ni = 0; ni < 8; ni++)
                mma_bf16(num[mi][ni], ah, &sbl[(ni >> 1)*4 + (ni & 1)*2]);
#pragma unroll
            for (int ni = 0; ni < 8; ni++)
                mma_bf16(num[mi][ni], al, &sbh[(ni >> 1)*4 + (ni & 1)*2]);
        }
    }

    // den: quad reduce, then + q.Z
#pragma unroll
    for (int mi = 0; mi < 2; mi++)
#pragma unroll
        for (int hf = 0; hf < 2; hf++) {
            float d = den[mi][hf];
            d += __shfl_xor_sync(0xffffffffu, d, 1);
            d += __shfl_xor_sync(0xffffffffu, d, 2);
            int row = w*32 + mi*16 + (lane >> 2) + hf*8;
            float qz = 0.f;
            const char* qrh = sm + QHI_O + row*AP;
            const char* qrl = sm + QLO_O + row*AP;
#pragma unroll
            for (int dd = 0; dd < 32; dd++) {
                __nv_bfloat162 qh2 = *(const __nv_bfloat162*)(qrh + dd*4);
                __nv_bfloat162 ql2 = *(const __nv_bfloat162*)(qrl + dd*4);
                float2 z2 = *(const float2*)(sm + Z_O + dd*8);
                qz += (__bfloat162float(qh2.x) + __bfloat162float(ql2.x)) * z2.x
                    + (__bfloat162float(qh2.y) + __bfloat162float(ql2.y)) * z2.y;
            }
            den[mi][hf] = d + qz;
        }

    // divide + split-bf16 store to g_att
    const size_t mbase = (size_t)(b * LL + c * CH);
#pragma unroll
    for (int mi = 0; mi < 2; mi++)
#pragma unroll
        for (int hf = 0; hf < 2; hf++) {
            int row = w*32 + mi*16 + (lane >> 2) + hf*8;
            float inv = 1.f / fmaxf(den[mi][hf], 1e-6f);
            size_t ob = (mbase + row) * EE + h * DH;
#pragma unroll
            for (int ni = 0; ni < 8; ni++) {
                int e = ni*8 + (lane & 3)*2;
                float v0 = num[mi][ni][hf*2 + 0] * inv;
                float v1 = num[mi][ni][hf*2 + 1] * inv;
                uint32_t hi, lo;
                split2(v0, v1, hi, lo);
                *(uint32_t*)(g_att_hi + ob + e) = hi;
                *(uint32_t*)(g_att_lo + ob + e) = lo;
            }
        }
}

// ---------------- launch ----------------
extern "C" void kernel_launch(void* const* d_in, const int* in_sizes, int n_in,
                              void* d_out, int out_size)
{
    const float* x    = (const float*)d_in[0];   // [B, L, E]
    const float* Wqkv = (const float*)d_in[1];   // [3E, E]
    const float* Wout = (const float*)d_in[2];   // [E, E]
    float* out = (float*)d_out;                  // [B, L, E]

    cudaFuncSetAttribute(attn_core_kernel,
                         cudaFuncAttributeMaxDynamicSharedMemorySize, ATTN_SMEM);
    const int gemm_smem = 2 * STAGE2;  // 81920
    cudaFuncSetAttribute(hmma_gemm_kernel<0>,
                         cudaFuncAttributeMaxDynamicSharedMemorySize, gemm_smem);
    cudaFuncSetAttribute(hmma_gemm_kernel<1>,
                         cudaFuncAttributeMaxDynamicSharedMemorySize, gemm_smem);

    // 0) split-bf16 conversion of inputs
    convert_kernel<0><<<(M1*EE/4 + 255)/256, 256>>>(x, M1*EE/4);
    convert_kernel<1><<<(NQKV*EE/4 + 255)/256, 256>>>(Wqkv, NQKV*EE/4);
    convert_kernel<2><<<(EE*EE/4 + 255)/256, 256>>>(Wout, EE*EE/4);

    // 1) QKV GEMM + feature-map -> bf16 hi/lo q/k/v
    {
        dim3 grid(NQKV/128, M1/128);  // (24, 64)
        hmma_gemm_kernel<0><<<grid, 256, gemm_smem>>>(nullptr);
    }
    // 2) per-chunk Gram matrices
    {
        dim3 grid(NCH, HH, BB);
        chunk_kv_kernel<<<grid, 256>>>();
    }
    // 3) exclusive prefix (emits S^T bf16 hi/lo + Z)
    prefix_kernel<<<BB*HH, 256>>>();
    // 4) attention core (HMMA, writes split-bf16 g_att)
    {
        dim3 grid(NCH, HH, BB);
        attn_core_kernel<<<grid, 256, ATTN_SMEM>>>();
    }
    // 5) output GEMM: out = att @ Wout^T
    {
        dim3 grid(EE/128, M1/128);    // (8, 64)
        hmma_gemm_kernel<1><<<grid, 256, gemm_smem>>>(out);
    }
}

// round 9
// speedup vs baseline: 4.5656x; 2.0593x over previous
#include <cuda_runtime.h>
#include <cuda_fp16.h>
#include <math.h>
#include <stdint.h>

#define BB 2
#define LL 4096
#define EE 1024
#define HH 16
#define DH 64
#define CH 256
#define NCH 16
#define M1 (BB*LL)      // 8192
#define NQKV (3*EE)     // 3072

// ---------------- scratch (static device globals; no allocation) ----------------
__device__ __align__(16) __half g_xh[(size_t)M1*EE];
__device__ __align__(16) __half g_wqkvh[(size_t)NQKV*EE];
__device__ __align__(16) __half g_wouth[(size_t)EE*EE];
__device__ __align__(16) __half g_atth[(size_t)M1*EE];

__device__ __align__(16) __half g_qh[(size_t)BB*HH*LL*DH];
__device__ __align__(16) __half g_kh[(size_t)BB*HH*LL*DH];
__device__ __align__(16) __half g_vh[(size_t)BB*HH*LL*DH];

__device__ float g_G[(size_t)BB*HH*NCH*DH*DH];
__device__ __align__(16) __half g_STh[(size_t)BB*HH*NCH*DH*DH];
__device__ float g_zc[(size_t)BB*HH*NCH*DH];
__device__ float g_Z[(size_t)BB*HH*NCH*DH];

// ---------------- helpers ----------------
__device__ __forceinline__ uint32_t smem_u32(const void* p) {
    uint32_t a;
    asm("{ .reg .u64 t; cvta.to.shared.u64 t, %1; cvt.u32.u64 %0, t; }" : "=r"(a) : "l"(p));
    return a;
}
__device__ __forceinline__ void ldmx4(uint32_t* r, uint32_t a) {
    asm volatile("ldmatrix.sync.aligned.m8n8.x4.shared.b16 {%0,%1,%2,%3}, [%4];"
        : "=r"(r[0]), "=r"(r[1]), "=r"(r[2]), "=r"(r[3]) : "r"(a));
}
__device__ __forceinline__ void mma_f16(float* d, const uint32_t* a, const uint32_t* b) {
    asm volatile(
        "mma.sync.aligned.m16n8k16.row.col.f32.f16.f16.f32 "
        "{%0,%1,%2,%3}, {%4,%5,%6,%7}, {%8,%9}, {%0,%1,%2,%3};"
        : "+f"(d[0]), "+f"(d[1]), "+f"(d[2]), "+f"(d[3])
        : "r"(a[0]), "r"(a[1]), "r"(a[2]), "r"(a[3]), "r"(b[0]), "r"(b[1]));
}
__device__ __forceinline__ uint32_t packh2(float a, float b) {
    __half2 t = __halves2half2(__float2half_rn(a), __float2half_rn(b));
    return *(uint32_t*)&t;
}

#define CP_ASYNC16(s, g) \
    asm volatile("cp.async.cg.shared.global [%0], [%1], 16;" :: "r"(s), "l"(g))
#define CP_COMMIT() asm volatile("cp.async.commit_group;")
#define CP_WAIT1()  asm volatile("cp.async.wait_group 1;")
#define CP_WAIT0()  asm volatile("cp.async.wait_group 0;")

// ---------------- fp32 -> fp16 converter ----------------
template<int W>
__global__ __launch_bounds__(256)
void convert_kernel(const float* __restrict__ src, int n4)
{
    __half* dst = (W == 0) ? g_xh : (W == 1) ? g_wqkvh : g_wouth;
    int i = blockIdx.x * 256 + threadIdx.x;
    if (i >= n4) return;
    float4 v = ((const float4*)src)[i];
    ((__half2*)dst)[i*2 + 0] = __halves2half2(__float2half_rn(v.x), __float2half_rn(v.y));
    ((__half2*)dst)[i*2 + 1] = __halves2half2(__float2half_rn(v.z), __float2half_rn(v.w));
}

// ---------------- fp16 HMMA GEMM, cp.async double-buffered, BK=64 ----------------
// C[M,N] = A[M,K] * B[N,K]^T, fp32 accumulate, 1 MMA per tile pair.
// Block 128x128, 4 warps (2x2), warp tile 64x64. 128 threads.
// MODE 0: A=g_xh, B=g_wqkvh (N=3072), epilogue feature map -> fp16 q/k/v
// MODE 1: A=g_atth, B=g_wouth (N=1024), plain fp32 store to C
#define GP 144
#define GTILE (128*GP)      // 18432
#define GSTAGE (2*GTILE)    // 36864

template<int MODE>
__global__ __launch_bounds__(128, 2)
void hmma_gemm_kernel(float* __restrict__ C)
{
    const __half* __restrict__ A = (MODE == 0) ? g_xh : g_atth;
    const __half* __restrict__ B = (MODE == 0) ? g_wqkvh : g_wouth;

    const int m0 = blockIdx.y * 128;
    const int n0 = blockIdx.x * 128;
    const int tid = threadIdx.x;
    const int wid = tid >> 5;
    const int lane = tid & 31;
    const int wm = (wid >> 1) * 64;
    const int wn = (wid & 1) * 64;

    extern __shared__ char smc[];
    const uint32_t base = smem_u32(smc);

    float acc[4][8][4];
#pragma unroll
    for (int a = 0; a < 4; a++)
#pragma unroll
        for (int b = 0; b < 8; b++)
#pragma unroll
            for (int c = 0; c < 4; c++) acc[a][b][c] = 0.f;

    const int g = lane >> 3, lr = lane & 7;
    const int a_row  = ((g & 1) << 3) + lr;
    const int a_xtra = (g & 2) ? 16 : 0;
    const int b_row  = ((g >> 1) << 3) + lr;
    const int b_xtra = (g & 1) ? 16 : 0;

    auto prefetch = [&](int kc, int stg) {
        const int kb = kc * 64;
        const uint32_t sb = base + stg * GSTAGE;
#pragma unroll
        for (int i = 0; i < 8; i++) {
            int s = tid + i * 128;          // 0..1023
            int row = s >> 3, c16 = s & 7;
            uint32_t so = (uint32_t)(row * GP + c16 * 16);
            CP_ASYNC16(sb + so,         __cvta_generic_to_global(A + (size_t)(m0 + row) * EE + kb + c16 * 8));
            CP_ASYNC16(sb + GTILE + so, __cvta_generic_to_global(B + (size_t)(n0 + row) * EE + kb + c16 * 8));
        }
    };

    prefetch(0, 0); CP_COMMIT();

    for (int kc = 0; kc < 16; kc++) {
        const int stg = kc & 1;
        if (kc + 1 < 16) { prefetch(kc + 1, stg ^ 1); CP_COMMIT(); CP_WAIT1(); }
        else             { CP_WAIT0(); }
        __syncthreads();

        const uint32_t sb = base + stg * GSTAGE;
#pragma unroll
        for (int t = 0; t < 4; t++) {
            uint32_t bf[16];
#pragma unroll
            for (int np = 0; np < 4; np++)
                ldmx4(bf + np*4, sb + GTILE + (uint32_t)((wn + np*16 + b_row) * GP + t*32 + b_xtra));
            uint32_t af[16];
#pragma unroll
            for (int mi = 0; mi < 4; mi++)
                ldmx4(af + mi*4, sb + (uint32_t)((wm + mi*16 + a_row) * GP + t*32 + a_xtra));
#pragma unroll
            for (int mi = 0; mi < 4; mi++)
#pragma unroll
                for (int ni = 0; ni < 8; ni++)
                    mma_f16(acc[mi][ni], af + mi*4, &bf[(ni >> 1)*4 + (ni & 1)*2]);
        }
        __syncthreads();
    }

    // epilogue
#pragma unroll
    for (int mi = 0; mi < 4; mi++) {
        int mrow = m0 + wm + mi*16 + (lane >> 2);
#pragma unroll
        for (int half = 0; half < 2; half++) {
            int m = mrow + half * 8;
#pragma unroll
            for (int ni = 0; ni < 8; ni++) {
                int n = n0 + wn + ni*8 + (lane & 3)*2;
                float v0 = acc[mi][ni][half*2 + 0];
                float v1 = acc[mi][ni][half*2 + 1];
                if (MODE == 1) {
                    *(float2*)(C + (size_t)m * EE + n) = make_float2(v0, v1);
                } else {
                    int s = n >> 10, h = (n >> 6) & 15, d = n & 63;
                    int bidx = m >> 12, l = m & 4095;
                    float r0, r1;
                    if (s == 0) {
                        r0 = (v0 > 0.f ? v0 + 1.f : expf(v0)) * 0.125f;
                        r1 = (v1 > 0.f ? v1 + 1.f : expf(v1)) * 0.125f;
                    } else if (s == 1) {
                        r0 = (v0 > 0.f ? v0 + 1.f : expf(v0));
                        r1 = (v1 > 0.f ? v1 + 1.f : expf(v1));
                    } else {
                        r0 = v0; r1 = v1;
                    }
                    __half* dst = (s == 0) ? g_qh : (s == 1) ? g_kh : g_vh;
                    size_t off = ((size_t)(bidx*HH + h) * LL + l) * DH + d;
                    *(uint32_t*)(dst + off) = packh2(r0, r1);
                }
            }
        }
    }
}

// ---------------- per-chunk Gram: G = K_c^T V_c  (64x64), z = sum K_c ----------------
__global__ __launch_bounds__(256)
void chunk_kv_kernel()
{
    const int c = blockIdx.x, h = blockIdx.y, b = blockIdx.z;
    const int bh = b * HH + h;
    const size_t tokbase = ((size_t)bh * LL + c * CH) * DH;
    const __half* kh = g_kh + tokbase;
    const __half* vh = g_vh + tokbase;

    __shared__ float ks[64][65];
    __shared__ float vs[64][65];

    const int tid = threadIdx.x;
    const int tx = tid & 15, ty = tid >> 4;

    float acc[4][4];
#pragma unroll
    for (int i = 0; i < 4; i++)
#pragma unroll
        for (int j = 0; j < 4; j++) acc[i][j] = 0.f;
    float zacc = 0.f;

    for (int lt = 0; lt < 4; lt++) {
#pragma unroll
        for (int t = 0; t < 4; t++) {
            int idx = tid + t * 256;
            int row = idx >> 4, c4 = idx & 15;
            size_t off = (size_t)(lt*64 + row) * DH + c4 * 4;
            float2 a0 = __half22float2(*(const __half2*)(kh + off));
            float2 a1 = __half22float2(*(const __half2*)(kh + off + 2));
            ks[row][c4*4+0] = a0.x; ks[row][c4*4+1] = a0.y;
            ks[row][c4*4+2] = a1.x; ks[row][c4*4+3] = a1.y;
            float2 b0 = __half22float2(*(const __half2*)(vh + off));
            float2 b1 = __half22float2(*(const __half2*)(vh + off + 2));
            vs[row][c4*4+0] = b0.x; vs[row][c4*4+1] = b0.y;
            vs[row][c4*4+2] = b1.x; vs[row][c4*4+3] = b1.y;
        }
        __syncthreads();
#pragma unroll 8
        for (int l = 0; l < 64; l++) {
            float a[4], bb[4];
#pragma unroll
            for (int i = 0; i < 4; i++) a[i] = ks[l][ty*4 + i];
#pragma unroll
            for (int j = 0; j < 4; j++) bb[j] = vs[l][tx*4 + j];
#pragma unroll
            for (int i = 0; i < 4; i++)
#pragma unroll
                for (int j = 0; j < 4; j++) acc[i][j] += a[i] * bb[j];
        }
        if (tid < 64) {
#pragma unroll 8
            for (int l = 0; l < 64; l++) zacc += ks[l][tid];
        }
        __syncthreads();
    }

    float* Gout = g_G + ((size_t)bh * NCH + c) * DH * DH;
#pragma unroll
    for (int i = 0; i < 4; i++)
#pragma unroll
        for (int j = 0; j < 4; j++)
            Gout[(ty*4 + i) * DH + tx*4 + j] = acc[i][j];
    if (tid < 64) g_zc[((size_t)bh * NCH + c) * DH + tid] = zacc;
}

// ---------------- exclusive prefix over chunks; emits S^T as fp16 ----------------
__global__ __launch_bounds__(256)
void prefix_kernel()
{
    const int bh = blockIdx.x;
    const int tid = threadIdx.x;
    for (int idx = tid; idx < DH*DH; idx += 256) {
        int d = idx >> 6, e = idx & 63;
        float run = 0.f;
        for (int c = 0; c < NCH; c++) {
            size_t gbase = ((size_t)bh * NCH + c) * DH * DH;
            g_STh[gbase + e*DH + d] = __float2half_rn(run);
            run += g_G[gbase + idx];
        }
    }
    if (tid < DH) {
        float run = 0.f;
        for (int c = 0; c < NCH; c++) {
            size_t o = ((size_t)bh * NCH + c) * DH + tid;
            g_Z[o] = run;
            run += g_zc[o];
        }
    }
}

// ---------------- attention core (fp16 HMMA): per (b,h,c), 256x64 tile ----------------
#define AP 144
#define QH_O  0
#define KH_O  36864
#define VT_O  46080
#define ST_O  55296
#define Z_O   64512
#define ATTN_SMEM (Z_O + 256)

__global__ __launch_bounds__(256, 1)
void attn_core_kernel()
{
    const int c = blockIdx.x, h = blockIdx.y, b = blockIdx.z;
    const int bh = b * HH + h;
    const size_t tokbase = (size_t)bh * LL + c * CH;

    extern __shared__ char sm[];
    const uint32_t sbase = smem_u32(sm);

    const int tid = threadIdx.x;
    const int w = tid >> 5;
    const int lane = tid & 31;
    const int g = lane >> 3, lr = lane & 7;
    const int a_row  = ((g & 1) << 3) + lr;
    const int a_xtra = (g & 2) ? 16 : 0;
    const int b_row  = ((g >> 1) << 3) + lr;
    const int b_xtra = (g & 1) ? 16 : 0;

    // load Q (256x64)
    {
        const __half* qh = g_qh + tokbase * DH;
#pragma unroll
        for (int t = 0; t < 8; t++) {
            int idx = tid + t * 256;
            int row = idx >> 3, c16 = idx & 7;
            *(uint4*)(sm + QH_O + row*AP + c16*16) = *(const uint4*)(qh + (size_t)row*DH + c16*8);
        }
    }
    // load S^T (64x64) + Z
    {
        const size_t stb = ((size_t)bh * NCH + c) * DH * DH;
#pragma unroll
        for (int t = 0; t < 2; t++) {
            int idx = tid + t * 256;
            int row = idx >> 3, c16 = idx & 7;
            *(uint4*)(sm + ST_O + row*AP + c16*16) = *(const uint4*)(g_STh + stb + (size_t)row*DH + c16*8);
        }
        if (tid < DH) *(float*)(sm + Z_O + tid*4) = g_Z[((size_t)bh * NCH + c) * DH + tid];
    }

    float num[2][8][4];
#pragma unroll
    for (int mi = 0; mi < 2; mi++)
#pragma unroll
        for (int ni = 0; ni < 8; ni++)
#pragma unroll
            for (int e = 0; e < 4; e++) num[mi][ni][e] = 0.f;
    float den[2][2] = {{0.f, 0.f}, {0.f, 0.f}};

    for (int jb = 0; jb < 4; jb++) {
        __syncthreads();   // strip buffers free (also orders Q/ST loads on jb==0)
        // load K strip (64x64)
        {
            const __half* kh = g_kh + (tokbase + jb*64) * DH;
#pragma unroll
            for (int t = 0; t < 2; t++) {
                int idx = tid + t * 256;
                int row = idx >> 3, c16 = idx & 7;
                *(uint4*)(sm + KH_O + row*AP + c16*16) = *(const uint4*)(kh + (size_t)row*DH + c16*8);
            }
        }
        // load + transpose V strip: Vt[e][m]
        {
            const __half* vh = g_vh + (tokbase + jb*64) * DH;
#pragma unroll
            for (int t = 0; t < 4; t++) {
                int s = tid + t * 256;
                int m = s >> 4, e = (s & 15) * 4;
                __half2 h0 = *(const __half2*)(vh + (size_t)m*DH + e);
                __half2 h1 = *(const __half2*)(vh + (size_t)m*DH + e + 2);
                *(__half*)(sm + VT_O + (e+0)*AP + m*2) = __low2half(h0);
                *(__half*)(sm + VT_O + (e+1)*AP + m*2) = __high2half(h0);
                *(__half*)(sm + VT_O + (e+2)*AP + m*2) = __low2half(h1);
                *(__half*)(sm + VT_O + (e+3)*AP + m*2) = __high2half(h1);
            }
        }
        __syncthreads();

        // GEMM1: P = Q * Kstrip^T  (warp: 32x64, k=64)
        float pacc[2][8][4];
#pragma unroll
        for (int mi = 0; mi < 2; mi++)
#pragma unroll
            for (int ni = 0; ni < 8; ni++)
#pragma unroll
                for (int e = 0; e < 4; e++) pacc[mi][ni][e] = 0.f;

#pragma unroll
        for (int t = 0; t < 4; t++) {
            uint32_t kb[16];
#pragma unroll
            for (int np = 0; np < 4; np++)
                ldmx4(kb + np*4, sbase + KH_O + (uint32_t)((np*16 + b_row)*AP + t*32 + b_xtra));
#pragma unroll
            for (int mi = 0; mi < 2; mi++) {
                uint32_t ah[4];
                ldmx4(ah, sbase + QH_O + (uint32_t)((w*32 + mi*16 + a_row)*AP + t*32 + a_xtra));
#pragma unroll
                for (int ni = 0; ni < 8; ni++)
                    mma_f16(pacc[mi][ni], ah, &kb[(ni >> 1)*4 + (ni & 1)*2]);
            }
        }

        // causal mask + den partials
#pragma unroll
        for (int mi = 0; mi < 2; mi++)
#pragma unroll
            for (int ni = 0; ni < 8; ni++)
#pragma unroll
                for (int e = 0; e < 4; e++) {
                    int row = w*32 + mi*16 + (lane >> 2) + (e >> 1)*8;
                    int col = jb*64 + ni*8 + (lane & 3)*2 + (e & 1);
                    if (col > row) pacc[mi][ni][e] = 0.f;
                    else           den[mi][e >> 1] += pacc[mi][ni][e];
                }

        // GEMM2: num += P * Vstrip  (k = strip token dim, via Vt)
#pragma unroll
        for (int t = 0; t < 4; t++) {
            uint32_t vb[16];
#pragma unroll
            for (int np = 0; np < 4; np++)
                ldmx4(vb + np*4, sbase + VT_O + (uint32_t)((np*16 + b_row)*AP + t*32 + b_xtra));
#pragma unroll
            for (int mi = 0; mi < 2; mi++) {
                // acc->A-frag identity: tiles 2t & 2t+1 supply k16 tile t
                uint32_t ph[4];
                ph[0] = packh2(pacc[mi][2*t][0],   pacc[mi][2*t][1]);
                ph[1] = packh2(pacc[mi][2*t][2],   pacc[mi][2*t][3]);
                ph[2] = packh2(pacc[mi][2*t+1][0], pacc[mi][2*t+1][1]);
                ph[3] = packh2(pacc[mi][2*t+1][2], pacc[mi][2*t+1][3]);
#pragma unroll
                for (int ni = 0; ni < 8; ni++)
                    mma_f16(num[mi][ni], ph, &vb[(ni >> 1)*4 + (ni & 1)*2]);
            }
        }
    }

    // inter-chunk: num += Q * S (B = S^T)
#pragma unroll
    for (int t = 0; t < 4; t++) {
        uint32_t sb[16];
#pragma unroll
        for (int np = 0; np < 4; np++)
            ldmx4(sb + np*4, sbase + ST_O + (uint32_t)((np*16 + b_row)*AP + t*32 + b_xtra));
#pragma unroll
        for (int mi = 0; mi < 2; mi++) {
            uint32_t ah[4];
            ldmx4(ah, sbase + QH_O + (uint32_t)((w*32 + mi*16 + a_row)*AP + t*32 + a_xtra));
#pragma unroll
            for (int ni = 0; ni < 8; ni++)
                mma_f16(num[mi][ni], ah, &sb[(ni >> 1)*4 + (ni & 1)*2]);
        }
    }

    // den: quad reduce, then + q.Z
#pragma unroll
    for (int mi = 0; mi < 2; mi++)
#pragma unroll
        for (int hf = 0; hf < 2; hf++) {
            float d = den[mi][hf];
            d += __shfl_xor_sync(0xffffffffu, d, 1);
            d += __shfl_xor_sync(0xffffffffu, d, 2);
            int row = w*32 + mi*16 + (lane >> 2) + hf*8;
            float qz = 0.f;
            const char* qr = sm + QH_O + row*AP;
#pragma unroll
            for (int dd = 0; dd < 32; dd++) {
                float2 q2 = __half22float2(*(const __half2*)(qr + dd*4));
                float2 z2 = *(const float2*)(sm + Z_O + dd*8);
                qz += q2.x * z2.x + q2.y * z2.y;
            }
            den[mi][hf] = d + qz;
        }

    // divide + fp16 store to g_atth
    const size_t mbase = (size_t)(b * LL + c * CH);
#pragma unroll
    for (int mi = 0; mi < 2; mi++)
#pragma unroll
        for (int hf = 0; hf < 2; hf++) {
            int row = w*32 + mi*16 + (lane >> 2) + hf*8;
            float inv = 1.f / fmaxf(den[mi][hf], 1e-6f);
            size_t ob = (mbase + row) * EE + h * DH;
#pragma unroll
            for (int ni = 0; ni < 8; ni++) {
                int e = ni*8 + (lane & 3)*2;
                *(uint32_t*)(g_atth + ob + e) =
                    packh2(num[mi][ni][hf*2 + 0] * inv, num[mi][ni][hf*2 + 1] * inv);
            }
        }
}

// ---------------- launch ----------------
extern "C" void kernel_launch(void* const* d_in, const int* in_sizes, int n_in,
                              void* d_out, int out_size)
{
    const float* x    = (const float*)d_in[0];   // [B, L, E]
    const float* Wqkv = (const float*)d_in[1];   // [3E, E]
    const float* Wout = (const float*)d_in[2];   // [E, E]
    float* out = (float*)d_out;                  // [B, L, E]

    cudaFuncSetAttribute(attn_core_kernel,
                         cudaFuncAttributeMaxDynamicSharedMemorySize, ATTN_SMEM);
    const int gemm_smem = 2 * GSTAGE;  // 73728
    cudaFuncSetAttribute(hmma_gemm_kernel<0>,
                         cudaFuncAttributeMaxDynamicSharedMemorySize, gemm_smem);
    cudaFuncSetAttribute(hmma_gemm_kernel<1>,
                         cudaFuncAttributeMaxDynamicSharedMemorySize, gemm_smem);

    // 0) fp16 conversion of inputs
    convert_kernel<0><<<(M1*EE/4 + 255)/256, 256>>>(x, M1*EE/4);
    convert_kernel<1><<<(NQKV*EE/4 + 255)/256, 256>>>(Wqkv, NQKV*EE/4);
    convert_kernel<2><<<(EE*EE/4 + 255)/256, 256>>>(Wout, EE*EE/4);

    // 1) QKV GEMM + feature-map -> fp16 q/k/v
    {
        dim3 grid(NQKV/128, M1/128);  // (24, 64)
        hmma_gemm_kernel<0><<<grid, 128, gemm_smem>>>(nullptr);
    }
    // 2) per-chunk Gram matrices
    {
        dim3 grid(NCH, HH, BB);
        chunk_kv_kernel<<<grid, 256>>>();
    }
    // 3) exclusive prefix (emits S^T fp16 + Z)
    prefix_kernel<<<BB*HH, 256>>>();
    // 4) attention core (fp16 HMMA, writes fp16 g_atth)
    {
        dim3 grid(NCH, HH, BB);
        attn_core_kernel<<<grid, 256, ATTN_SMEM>>>();
    }
    // 5) output GEMM: out = att @ Wout^T
    {
        dim3 grid(EE/128, M1/128);    // (8, 64)
        hmma_gemm_kernel<1><<<grid, 128, gemm_smem>>>(out);
    }
}